// round 7
// baseline (speedup 1.0000x reference)
#include <cuda_runtime.h>
#include <cuda_bf16.h>
#include <math.h>
#include <stdint.h>

// ---------------------------------------------------------------------------
// Problem constants
// ---------------------------------------------------------------------------
#define B_   2
#define L_   8192
#define QN   32
#define IN_  96
#define D_   512
#define H_   8
#define DH_  64
#define FF_  2048
#define SCALE_ 0.125f
#define NEGV  (-1.0e9f)

constexpr size_t S_  = (size_t)B_ * L_ * D_;      // 8,388,608
constexpr size_t BLH = (size_t)B_ * L_ * H_;      // 131,072
constexpr size_t SM  = (size_t)B_ * 128 * D_;     // 131,072  (comb rows)
constexpr size_t DD  = (size_t)D_ * D_;           // 262,144

// scratch layout (floats) inside one big __device__ buffer
constexpr size_t OFF_X    = 0;
constexpr size_t OFF_H    = S_;
constexpr size_t OFF_Q    = 2 * S_;
constexpr size_t OFF_K    = 3 * S_;
constexpr size_t OFF_V    = 4 * S_;
constexpr size_t OFF_OC   = 5 * S_;
constexpr size_t OFF_CTX  = 6 * S_;
constexpr size_t OFF_O5   = 7 * S_;            // 5 branch outputs (5*S_)
constexpr size_t OFF_FF   = 12 * S_;           // FFN hidden (4*S_)
constexpr size_t OFF_LSE5 = 16 * S_;           // 5 branch lse (5*BLH)
constexpr size_t OFF_COMB = OFF_LSE5 + 5 * BLH;
constexpr size_t OFF_HS   = OFF_COMB + SM;
constexpr size_t OFF_OS   = OFF_HS + SM;
constexpr size_t OFF_T    = OFF_OS + SM;
constexpr size_t OFF_FFS  = OFF_T + SM;
constexpr size_t OFF_QRY  = OFF_FFS + (size_t)B_ * 128 * FF_;
constexpr size_t OFF_PART = OFF_QRY + (size_t)B_ * QN * D_;
constexpr size_t OFF_PLSE = OFF_PART + (size_t)32 * B_ * QN * H_ * DH_;
constexpr size_t TOTAL_F  = OFF_PLSE + (size_t)32 * B_ * QN * H_;

__device__ float gbuf[TOTAL_F];

// ---------------------------------------------------------------------------
// Elementwise / small kernels
// ---------------------------------------------------------------------------
__global__ void copy4_k(float* __restrict__ dst, const float* __restrict__ src, size_t n4) {
    size_t i = (size_t)blockIdx.x * blockDim.x + threadIdx.x;
    size_t st = (size_t)gridDim.x * blockDim.x;
    for (; i < n4; i += st) ((float4*)dst)[i] = ((const float4*)src)[i];
}

__global__ void fill_k(float* __restrict__ dst, size_t n, float v) {
    size_t i = (size_t)blockIdx.x * blockDim.x + threadIdx.x;
    size_t st = (size_t)gridDim.x * blockDim.x;
    for (; i < n; i += st) dst[i] = v;
}

__global__ void axpyg_k(float* __restrict__ dst, const float* __restrict__ src,
                        const float* __restrict__ g, size_t n) {
    size_t i = (size_t)blockIdx.x * blockDim.x + threadIdx.x;
    size_t st = (size_t)gridDim.x * blockDim.x;
    for (; i < n; i += st) dst[i] = fmaf(g[i & (D_ - 1)], src[i], dst[i]);
}

__global__ void concat_k(float* __restrict__ comb, const float* __restrict__ q,
                         const float* __restrict__ ins) {
    size_t n = SM;
    size_t i = (size_t)blockIdx.x * blockDim.x + threadIdx.x;
    size_t st = (size_t)gridDim.x * blockDim.x;
    for (; i < n; i += st) {
        int b = (int)(i / (128 * D_));
        int rem = (int)(i % (128 * D_));
        int t = rem / D_, d = rem % D_;
        comb[i] = (t < QN) ? q[((size_t)b * QN + t) * D_ + d]
                           : ins[((size_t)b * IN_ + (t - QN)) * D_ + d];
    }
}

__global__ void slice_k(float* __restrict__ qry, const float* __restrict__ comb) {
    size_t n = (size_t)B_ * QN * D_;
    size_t i = (size_t)blockIdx.x * blockDim.x + threadIdx.x;
    size_t st = (size_t)gridDim.x * blockDim.x;
    for (; i < n; i += st) {
        int b = (int)(i / (QN * D_));
        int rem = (int)(i % (QN * D_));
        qry[i] = comb[(size_t)b * 128 * D_ + rem];
    }
}

// OUTPUT: d_out is FLOAT32. Reference output is bf16-quantized, so emit
// bf16-rounded values upcast to float32 for an exact match.
__global__ void out_f32_k(float* __restrict__ out, const float* __restrict__ x, size_t n) {
    size_t i = (size_t)blockIdx.x * blockDim.x + threadIdx.x;
    size_t st = (size_t)gridDim.x * blockDim.x;
    for (; i < n; i += st) out[i] = __bfloat162float(__float2bfloat16(x[i]));
}

// contexts[b,l,:] += pos_embed[pidx(b,l),:]
__global__ void add_pos_k(float* __restrict__ ctx, const int* __restrict__ coords,
                          const float* __restrict__ pe) {
    const int bl = blockIdx.x, tid = threadIdx.x;
    const int c0 = coords[bl * 2]     / 256;
    const int c1 = coords[bl * 2 + 1] / 256;
    const size_t pidx = (size_t)(c0 * 256 + c1) * D_;
    float4* dst = (float4*)(ctx + (size_t)bl * D_);
    const float4* src = (const float4*)(pe + pidx);
    float4 a = dst[tid], b = src[tid];
    a.x += b.x; a.y += b.y; a.z += b.z; a.w += b.w;
    dst[tid] = a;
}

// ---------------------------------------------------------------------------
// LayerNorm: one block (128 thr) per row of D=512. In-place safe.
// ---------------------------------------------------------------------------
__global__ __launch_bounds__(128) void layernorm_k(
    const float* __restrict__ x, float* __restrict__ y,
    const float* __restrict__ g, const float* __restrict__ bet) {
    const int row = blockIdx.x, tid = threadIdx.x;
    const float4 v = ((const float4*)(x + (size_t)row * D_))[tid];
    float s = v.x + v.y + v.z + v.w;
    float sq = v.x * v.x + v.y * v.y + v.z * v.z + v.w * v.w;
#pragma unroll
    for (int o = 16; o > 0; o >>= 1) {
        s  += __shfl_xor_sync(0xffffffffu, s, o);
        sq += __shfl_xor_sync(0xffffffffu, sq, o);
    }
    __shared__ float sh[8];
    if ((tid & 31) == 0) { sh[tid >> 5] = s; sh[4 + (tid >> 5)] = sq; }
    __syncthreads();
    s  = sh[0] + sh[1] + sh[2] + sh[3];
    sq = sh[4] + sh[5] + sh[6] + sh[7];
    const float mean = s * (1.0f / D_);
    const float var  = sq * (1.0f / D_) - mean * mean;
    const float rs = rsqrtf(var + 1e-5f);
    const float4 gv = ((const float4*)g)[tid];
    const float4 bv = ((const float4*)bet)[tid];
    float4 o;
    o.x = (v.x - mean) * rs * gv.x + bv.x;
    o.y = (v.y - mean) * rs * gv.y + bv.y;
    o.z = (v.z - mean) * rs * gv.z + bv.z;
    o.w = (v.w - mean) * rs * gv.w + bv.w;
    ((float4*)(y + (size_t)row * D_))[tid] = o;
}

// ---------------------------------------------------------------------------
// SGEMM (NT): C[M,N] = A[M,K] @ W[N,K]^T + bias[N]; flags: 1=accum, 2=gelu
// ---------------------------------------------------------------------------
__global__ __launch_bounds__(256) void gemm_nt(
    const float* __restrict__ A, const float* __restrict__ W,
    const float* __restrict__ bias, float* __restrict__ C,
    int M, int N, int K, int flags) {
    __shared__ float As[16 * 136];
    __shared__ float Bs[16 * 136];
    const int tid = threadIdx.x;
    const int bm = blockIdx.y * 128, bn = blockIdx.x * 128;
    const int tr = (tid & 15) * 8;
    const int tc = (tid >> 4) * 8;
    const int lr0 = tid >> 1;
    const int lk0 = (tid & 1) * 8;
    float acc[8][8];
#pragma unroll
    for (int x = 0; x < 8; x++)
#pragma unroll
        for (int y = 0; y < 8; y++) acc[x][y] = 0.f;

    for (int k0 = 0; k0 < K; k0 += 16) {
        {
            const int r = bm + lr0;
            float4 a0, a1;
            if (r < M) {
                const float* src = A + (size_t)r * K + k0 + lk0;
                a0 = *(const float4*)src; a1 = *(const float4*)(src + 4);
            } else {
                a0 = make_float4(0, 0, 0, 0); a1 = a0;
            }
            As[(lk0 + 0) * 136 + lr0] = a0.x; As[(lk0 + 1) * 136 + lr0] = a0.y;
            As[(lk0 + 2) * 136 + lr0] = a0.z; As[(lk0 + 3) * 136 + lr0] = a0.w;
            As[(lk0 + 4) * 136 + lr0] = a1.x; As[(lk0 + 5) * 136 + lr0] = a1.y;
            As[(lk0 + 6) * 136 + lr0] = a1.z; As[(lk0 + 7) * 136 + lr0] = a1.w;
            const float* srcb = W + (size_t)(bn + lr0) * K + k0 + lk0;
            float4 b0 = *(const float4*)srcb; float4 b1 = *(const float4*)(srcb + 4);
            Bs[(lk0 + 0) * 136 + lr0] = b0.x; Bs[(lk0 + 1) * 136 + lr0] = b0.y;
            Bs[(lk0 + 2) * 136 + lr0] = b0.z; Bs[(lk0 + 3) * 136 + lr0] = b0.w;
            Bs[(lk0 + 4) * 136 + lr0] = b1.x; Bs[(lk0 + 5) * 136 + lr0] = b1.y;
            Bs[(lk0 + 6) * 136 + lr0] = b1.z; Bs[(lk0 + 7) * 136 + lr0] = b1.w;
        }
        __syncthreads();
#pragma unroll
        for (int kk = 0; kk < 16; kk++) {
            const float* ar = As + kk * 136 + tr;
            const float* br = Bs + kk * 136 + tc;
            float4 a0 = *(const float4*)ar, a1 = *(const float4*)(ar + 4);
            float4 b0 = *(const float4*)br, b1 = *(const float4*)(br + 4);
            float ra[8] = {a0.x, a0.y, a0.z, a0.w, a1.x, a1.y, a1.z, a1.w};
            float rb[8] = {b0.x, b0.y, b0.z, b0.w, b1.x, b1.y, b1.z, b1.w};
#pragma unroll
            for (int x = 0; x < 8; x++)
#pragma unroll
                for (int y = 0; y < 8; y++)
                    acc[x][y] = fmaf(ra[x], rb[y], acc[x][y]);
        }
        __syncthreads();
    }
#pragma unroll
    for (int x = 0; x < 8; x++) {
        const int r = bm + tr + x;
        if (r >= M) break;
        float* crow = C + (size_t)r * N + bn + tc;
#pragma unroll
        for (int y = 0; y < 8; y++) {
            float c = acc[x][y] + bias[bn + tc + y];
            if (flags & 2) c = 0.5f * c * (1.0f + erff(c * 0.70710678118654752f));
            if (flags & 1) c += crow[y];
            crow[y] = c;
        }
    }
}

// ---------------------------------------------------------------------------
// Flash dilated-attention branch: one block per (b, seg, h, qtile-of-128).
// m = w/r = 512 gathered positions. 32-key tiles staged in smem.
// ---------------------------------------------------------------------------
__global__ __launch_bounds__(128) void dil_branch_k(
    const float* __restrict__ Qm, const float* __restrict__ Km, const float* __restrict__ Vm,
    float* __restrict__ ofb, float* __restrict__ lfb, int w, int r) {
    __shared__ float Ks[32 * 64];
    __shared__ float Vs[32 * 64];
    __shared__ float Ss[32 * 128];
    const int nseg = L_ / w;
    int t = blockIdx.x;
    const int qt = t & 3; t >>= 2;
    const int h = t & 7; t >>= 3;
    const int seg = t % nseg; const int b = t / nseg;
    const int base = seg * w + (h & (r - 1));      // r is a power of two
    const int tid = threadIdx.x;
    const int j = qt * 128 + tid;
    const size_t rowq = (size_t)b * L_ + base + (size_t)r * j;
    const float* qp = Qm + rowq * D_ + h * DH_;
    float q[64];
#pragma unroll
    for (int d = 0; d < 64; d += 4) {
        float4 tv = *(const float4*)(qp + d);
        q[d] = tv.x; q[d + 1] = tv.y; q[d + 2] = tv.z; q[d + 3] = tv.w;
    }
    float o[64];
#pragma unroll
    for (int d = 0; d < 64; d++) o[d] = 0.f;
    float mv = -INFINITY, ls = 0.f;

    for (int kt = 0; kt < 16; kt++) {
        __syncthreads();
        for (int li = tid; li < 512; li += 128) {
            const int kk = li >> 4, dq = (li & 15) << 2;
            const size_t gp = ((size_t)b * L_ + base + (size_t)r * (kt * 32 + kk)) * D_
                              + h * DH_ + dq;
            *(float4*)(Ks + kk * 64 + dq) = *(const float4*)(Km + gp);
            *(float4*)(Vs + kk * 64 + dq) = *(const float4*)(Vm + gp);
        }
        __syncthreads();
        float tmax = -INFINITY;
#pragma unroll 1
        for (int kk = 0; kk < 32; kk++) {
            const float* kr = Ks + kk * 64;
            float s = 0.f;
#pragma unroll
            for (int d = 0; d < 64; d += 4) {
                float4 kv = *(const float4*)(kr + d);
                s = fmaf(q[d], kv.x, s);     s = fmaf(q[d + 1], kv.y, s);
                s = fmaf(q[d + 2], kv.z, s); s = fmaf(q[d + 3], kv.w, s);
            }
            s *= SCALE_;
            Ss[kk * 128 + tid] = s;
            tmax = fmaxf(tmax, s);
        }
        const float mn = fmaxf(mv, tmax);
        const float corr = __expf(mv - mn);
        ls *= corr;
#pragma unroll
        for (int d = 0; d < 64; d++) o[d] *= corr;
#pragma unroll 1
        for (int kk = 0; kk < 32; kk++) {
            const float p = __expf(Ss[kk * 128 + tid] - mn);
            ls += p;
            const float* vr = Vs + kk * 64;
#pragma unroll
            for (int d = 0; d < 64; d += 4) {
                float4 vv = *(const float4*)(vr + d);
                o[d]     = fmaf(p, vv.x, o[d]);
                o[d + 1] = fmaf(p, vv.y, o[d + 1]);
                o[d + 2] = fmaf(p, vv.z, o[d + 2]);
                o[d + 3] = fmaf(p, vv.w, o[d + 3]);
            }
        }
        mv = mn;
    }
    const float inv = 1.0f / ls;
    float* op = ofb + rowq * D_ + h * DH_;
#pragma unroll
    for (int d = 0; d < 64; d += 4) {
        float4 tv = make_float4(o[d] * inv, o[d + 1] * inv, o[d + 2] * inv, o[d + 3] * inv);
        *(float4*)(op + d) = tv;
    }
    lfb[rowq * H_ + h] = mv + logf(ls);
}

// ---------------------------------------------------------------------------
// Flash generic attention partial (split-KV). grid (nsplit, B*H, qtiles).
// ---------------------------------------------------------------------------
__global__ __launch_bounds__(128) void attn_part_k(
    const float* __restrict__ Qm, const float* __restrict__ Km, const float* __restrict__ Vm,
    float* __restrict__ op_, float* __restrict__ lse_,
    int Tq, int Tk, int chunk) {
    __shared__ float Ks[32 * 64];
    __shared__ float Vs[32 * 64];
    __shared__ float Ss[32 * 128];
    const int split = blockIdx.x;
    const int b = blockIdx.y >> 3;
    const int h = blockIdx.y & 7;
    const int qt = blockIdx.z;
    const int tid = threadIdx.x;
    const int qi = qt * 128 + tid;
    const bool act = qi < Tq;
    const float* qp = Qm + ((size_t)b * Tq + (act ? qi : 0)) * D_ + h * DH_;
    float q[64];
#pragma unroll
    for (int d = 0; d < 64; d += 4) {
        float4 tv = *(const float4*)(qp + d);
        q[d] = tv.x; q[d + 1] = tv.y; q[d + 2] = tv.z; q[d + 3] = tv.w;
    }
    float o[64];
#pragma unroll
    for (int d = 0; d < 64; d++) o[d] = 0.f;
    float mv = -INFINITY, ls = 0.f;
    const int k0 = split * chunk;
    const int ntile = chunk / 32;

    for (int kt = 0; kt < ntile; kt++) {
        __syncthreads();
        for (int li = tid; li < 512; li += 128) {
            const int kk = li >> 4, dq = (li & 15) << 2;
            const size_t gp = ((size_t)b * Tk + k0 + kt * 32 + kk) * D_ + h * DH_ + dq;
            *(float4*)(Ks + kk * 64 + dq) = *(const float4*)(Km + gp);
            *(float4*)(Vs + kk * 64 + dq) = *(const float4*)(Vm + gp);
        }
        __syncthreads();
        float tmax = -INFINITY;
#pragma unroll 1
        for (int kk = 0; kk < 32; kk++) {
            const float* kr = Ks + kk * 64;
            float s = 0.f;
#pragma unroll
            for (int d = 0; d < 64; d += 4) {
                float4 kv = *(const float4*)(kr + d);
                s = fmaf(q[d], kv.x, s);     s = fmaf(q[d + 1], kv.y, s);
                s = fmaf(q[d + 2], kv.z, s); s = fmaf(q[d + 3], kv.w, s);
            }
            s *= SCALE_;
            Ss[kk * 128 + tid] = s;
            tmax = fmaxf(tmax, s);
        }
        const float mn = fmaxf(mv, tmax);
        const float corr = __expf(mv - mn);
        ls *= corr;
#pragma unroll
        for (int d = 0; d < 64; d++) o[d] *= corr;
#pragma unroll 1
        for (int kk = 0; kk < 32; kk++) {
            const float p = __expf(Ss[kk * 128 + tid] - mn);
            ls += p;
            const float* vr = Vs + kk * 64;
#pragma unroll
            for (int d = 0; d < 64; d += 4) {
                float4 vv = *(const float4*)(vr + d);
                o[d]     = fmaf(p, vv.x, o[d]);
                o[d + 1] = fmaf(p, vv.y, o[d + 1]);
                o[d + 2] = fmaf(p, vv.z, o[d + 2]);
                o[d + 3] = fmaf(p, vv.w, o[d + 3]);
            }
        }
        mv = mn;
    }
    if (act) {
        const size_t RH = (size_t)B_ * Tq * H_;
        const size_t idx = (size_t)split * RH + ((size_t)b * Tq + qi) * H_ + h;
        const float inv = 1.0f / ls;
        float* op = op_ + idx * 64;
#pragma unroll
        for (int d = 0; d < 64; d += 4) {
            float4 tv = make_float4(o[d] * inv, o[d + 1] * inv, o[d + 2] * inv, o[d + 3] * inv);
            *(float4*)(op + d) = tv;
        }
        lse_[idx] = mv + logf(ls);
    }
}

// ---------------------------------------------------------------------------
// LSE-weighted combine; branches with lse <= -1e8 (uncovered) skipped.
// ---------------------------------------------------------------------------
__global__ __launch_bounds__(64) void combine_k(
    const float* __restrict__ op, const float* __restrict__ lse,
    float* __restrict__ out, int ns, size_t RH) {
    const size_t i = blockIdx.x;
    const int tid = threadIdx.x;
    float m = -INFINITY;
    for (int s = 0; s < ns; s++) {
        const float l = lse[(size_t)s * RH + i];
        if (l > -1e8f) m = fmaxf(m, l);
    }
    float tot = 0.f, acc = 0.f;
    for (int s = 0; s < ns; s++) {
        const float l = lse[(size_t)s * RH + i];
        if (l > -1e8f) {
            const float w = __expf(l - m);
            tot += w;
            acc = fmaf(w, op[((size_t)s * RH + i) * 64 + tid], acc);
        }
    }
    out[i * 64 + tid] = acc / tot;
}

// ---------------------------------------------------------------------------
// Host orchestration
// ---------------------------------------------------------------------------
static inline void gemm(const float* A, const float* W, const float* bias, float* C,
                        int M, int N, int K, int flags) {
    dim3 g(N / 128, (M + 127) / 128);
    gemm_nt<<<g, 256>>>(A, W, bias, C, M, N, K, flags);
}

extern "C" void kernel_launch(void* const* d_in, const int* in_sizes, int n_in,
                              void* d_out, int out_size) {
    (void)in_sizes; (void)n_in; (void)out_size;
    const float* querys   = (const float*)d_in[0];
    const float* contexts = (const float*)d_in[1];
    const float* instr    = (const float*)d_in[2];
    const int*   coords   = (const int*)d_in[3];
    const float* pe       = (const float*)d_in[4];
    const float* qkv_w    = (const float*)d_in[5];
    const float* qkv_b    = (const float*)d_in[6];
    const float* ln_ln    = (const float*)d_in[7];
    const float* fc1_w    = (const float*)d_in[8];
    const float* fc1_b    = (const float*)d_in[9];
    const float* fc2_w    = (const float*)d_in[10];
    const float* fc2_b    = (const float*)d_in[11];
    const float* ln_fin   = (const float*)d_in[12];
    const float* sa_w     = (const float*)d_in[13];
    const float* sa_b     = (const float*)d_in[14];
    const float* sa_ln    = (const float*)d_in[15];
    const float* sa_g     = (const float*)d_in[16];
    const float* sa_f1w   = (const float*)d_in[17];
    const float* sa_f1b   = (const float*)d_in[18];
    const float* sa_f2w   = (const float*)d_in[19];
    const float* sa_f2b   = (const float*)d_in[20];
    const float* ca_w     = (const float*)d_in[21];
    const float* ca_b     = (const float*)d_in[22];
    const float* ca_ln    = (const float*)d_in[23];

    float* g;
    { void* p = nullptr; cudaGetSymbolAddress(&p, gbuf); g = (float*)p; }
    float *X = g + OFF_X, *Hb = g + OFF_H, *Qb = g + OFF_Q, *Kb = g + OFF_K,
          *Vb = g + OFF_V, *OC = g + OFF_OC, *CTX = g + OFF_CTX, *O5 = g + OFF_O5,
          *FFb = g + OFF_FF, *LSE5 = g + OFF_LSE5, *COMB = g + OFF_COMB,
          *HS = g + OFF_HS, *OS = g + OFF_OS, *Tt = g + OFF_T, *FFS = g + OFF_FFS,
          *QRY = g + OFF_QRY, *PART = g + OFF_PART, *PLSE = g + OFF_PLSE;

    copy4_k<<<4096, 256>>>(CTX, contexts, S_ / 4);
    add_pos_k<<<B_ * L_, 128>>>(CTX, coords, pe);
    copy4_k<<<64, 256>>>(QRY, querys, (size_t)B_ * QN * D_ / 4);

    const int WS[5] = {512, 1024, 2048, 4096, 8192};
    const int RS[5] = {1, 2, 4, 8, 16};

    for (int i = 0; i < 2; i++) {
        copy4_k<<<4096, 256>>>(X, CTX, S_ / 4);
        for (int j = 0; j < 2; j++) {
            const int ij = i * 2 + j;
            const float* lg0 = ln_ln + (size_t)((ij * 2 + 0) * 2) * D_;
            layernorm_k<<<B_ * L_, 128>>>(X, Hb, lg0, lg0 + D_);
            const float* Wq = qkv_w + (size_t)(ij * 4) * DD;
            const float* bq = qkv_b + (size_t)(ij * 4) * D_;
            gemm(Hb, Wq,          bq,          Qb, B_ * L_, D_, D_, 0);
            gemm(Hb, Wq + DD,     bq + D_,     Kb, B_ * L_, D_, D_, 0);
            gemm(Hb, Wq + 2 * DD, bq + 2 * D_, Vb, B_ * L_, D_, D_, 0);
            fill_k<<<2560, 256>>>(LSE5, 5 * BLH, NEGV);
            for (int br = 0; br < 5; br++) {
                const int w = WS[br], r = RS[br], nseg = L_ / w;
                dil_branch_k<<<B_ * nseg * H_ * 4, 128>>>(
                    Qb, Kb, Vb, O5 + (size_t)br * S_, LSE5 + (size_t)br * BLH, w, r);
            }
            combine_k<<<(unsigned)BLH, 64>>>(O5, LSE5, OC, 5, BLH);
            gemm(OC, Wq + 3 * DD, bq + 3 * D_, X, B_ * L_, D_, D_, 1);
            const float* lg1 = ln_ln + (size_t)((ij * 2 + 1) * 2) * D_;
            layernorm_k<<<B_ * L_, 128>>>(X, Hb, lg1, lg1 + D_);
            gemm(Hb, fc1_w + (size_t)ij * FF_ * D_, fc1_b + (size_t)ij * FF_,
                 FFb, B_ * L_, FF_, D_, 2);
            gemm(FFb, fc2_w + (size_t)ij * D_ * FF_, fc2_b + (size_t)ij * D_,
                 X, B_ * L_, D_, FF_, 1);
        }
        layernorm_k<<<B_ * L_, 128>>>(X, CTX, ln_fin + (size_t)i * 2 * D_,
                                      ln_fin + (size_t)i * 2 * D_ + D_);
        concat_k<<<512, 256>>>(COMB, QRY, instr);
        const float* sl0 = sa_ln + (size_t)((i * 2 + 0) * 2) * D_;
        layernorm_k<<<B_ * 128, 128>>>(COMB, HS, sl0, sl0 + D_);
        const float* Ws = sa_w + (size_t)i * 4 * DD;
        const float* bs = sa_b + (size_t)i * 4 * D_;
        gemm(HS, Ws,          bs,          Qb, B_ * 128, D_, D_, 0);
        gemm(HS, Ws + DD,     bs + D_,     Kb, B_ * 128, D_, D_, 0);
        gemm(HS, Ws + 2 * DD, bs + 2 * D_, Vb, B_ * 128, D_, D_, 0);
        attn_part_k<<<dim3(1, B_ * H_, 1), 128>>>(Qb, Kb, Vb, PART, PLSE, 128, 128, 128);
        combine_k<<<B_ * 128 * H_, 64>>>(PART, PLSE, OS, 1, (size_t)B_ * 128 * H_);
        gemm(OS, Ws + 3 * DD, bs + 3 * D_, Tt, B_ * 128, D_, D_, 0);
        axpyg_k<<<128, 256>>>(COMB, Tt, sa_g + (size_t)(i * 2 + 0) * D_, SM);
        const float* sl1 = sa_ln + (size_t)((i * 2 + 1) * 2) * D_;
        layernorm_k<<<B_ * 128, 128>>>(COMB, HS, sl1, sl1 + D_);
        gemm(HS, sa_f1w + (size_t)i * FF_ * D_, sa_f1b + (size_t)i * FF_,
             FFS, B_ * 128, FF_, D_, 2);
        gemm(FFS, sa_f2w + (size_t)i * D_ * FF_, sa_f2b + (size_t)i * D_,
             Tt, B_ * 128, D_, FF_, 0);
        axpyg_k<<<128, 256>>>(COMB, Tt, sa_g + (size_t)(i * 2 + 1) * D_, SM);
        slice_k<<<32, 256>>>(QRY, COMB);
        const float* Wc = ca_w + (size_t)i * 4 * DD;
        const float* bc = ca_b + (size_t)i * 4 * D_;
        gemm(QRY, Wc,          bc,          Qb, B_ * QN, D_, D_, 0);
        gemm(CTX, Wc + DD,     bc + D_,     Kb, B_ * L_, D_, D_, 0);
        gemm(CTX, Wc + 2 * DD, bc + 2 * D_, Vb, B_ * L_, D_, D_, 0);
        attn_part_k<<<dim3(32, B_ * H_, 1), 128>>>(Qb, Kb, Vb, PART, PLSE, QN, L_, 256);
        combine_k<<<B_ * QN * H_, 64>>>(PART, PLSE, OS, 32, (size_t)B_ * QN * H_);
        gemm(OS, Wc + 3 * DD, bc + 3 * D_, QRY, B_ * QN, D_, D_, 1);
        layernorm_k<<<B_ * QN, 128>>>(QRY, QRY, ca_ln + (size_t)i * 2 * D_,
                                      ca_ln + (size_t)i * 2 * D_ + D_);
    }
    out_f32_k<<<32, 256>>>((float*)d_out, QRY, (size_t)B_ * QN * D_);
}

// round 12
// speedup vs baseline: 1.3167x; 1.3167x over previous
#include <cuda_runtime.h>
#include <cuda_bf16.h>
#include <math.h>
#include <stdint.h>

// ---------------------------------------------------------------------------
// Problem constants
// ---------------------------------------------------------------------------
#define B_   2
#define L_   8192
#define QN   32
#define IN_  96
#define D_   512
#define H_   8
#define DH_  64
#define FF_  2048
#define SCALE_ 0.125f
#define NEGV  (-1.0e9f)

constexpr size_t S_  = (size_t)B_ * L_ * D_;
constexpr size_t BLH = (size_t)B_ * L_ * H_;
constexpr size_t SM  = (size_t)B_ * 128 * D_;
constexpr size_t DD  = (size_t)D_ * D_;

constexpr size_t OFF_X    = 0;
constexpr size_t OFF_H    = S_;
constexpr size_t OFF_Q    = 2 * S_;
constexpr size_t OFF_K    = 3 * S_;
constexpr size_t OFF_V    = 4 * S_;
constexpr size_t OFF_OC   = 5 * S_;
constexpr size_t OFF_CTX  = 6 * S_;
constexpr size_t OFF_O5   = 7 * S_;
constexpr size_t OFF_FF   = 12 * S_;
constexpr size_t OFF_LSE5 = 16 * S_;
constexpr size_t OFF_COMB = OFF_LSE5 + 5 * BLH;
constexpr size_t OFF_HS   = OFF_COMB + SM;
constexpr size_t OFF_OS   = OFF_HS + SM;
constexpr size_t OFF_T    = OFF_OS + SM;
constexpr size_t OFF_FFS  = OFF_T + SM;
constexpr size_t OFF_QRY  = OFF_FFS + (size_t)B_ * 128 * FF_;
constexpr size_t OFF_PART = OFF_QRY + (size_t)B_ * QN * D_;
constexpr size_t OFF_PLSE = OFF_PART + (size_t)32 * B_ * QN * H_ * DH_;
constexpr size_t TOTAL_F  = OFF_PLSE + (size_t)32 * B_ * QN * H_;

__device__ float gbuf[TOTAL_F];

// ---------------------------------------------------------------------------
// mma.sync helpers (baseline PTX; no arch-'a' features)
// ---------------------------------------------------------------------------
__device__ __forceinline__ uint32_t smem_u32(const void* p) {
    uint32_t a;
    asm("{ .reg .u64 t; cvta.to.shared.u64 t, %1; cvt.u32.u64 %0, t; }" : "=r"(a) : "l"(p));
    return a;
}
__device__ __forceinline__ void ldsm_x4(uint32_t& r0, uint32_t& r1, uint32_t& r2,
                                        uint32_t& r3, uint32_t addr) {
    asm volatile("ldmatrix.sync.aligned.m8n8.x4.shared.b16 {%0,%1,%2,%3}, [%4];"
                 : "=r"(r0), "=r"(r1), "=r"(r2), "=r"(r3) : "r"(addr));
}
__device__ __forceinline__ void mma_bf16(float* d, const uint32_t* a, uint32_t b0, uint32_t b1) {
    asm volatile(
        "mma.sync.aligned.m16n8k16.row.col.f32.bf16.bf16.f32 "
        "{%0,%1,%2,%3}, {%4,%5,%6,%7}, {%8,%9}, {%0,%1,%2,%3};"
        : "+f"(d[0]), "+f"(d[1]), "+f"(d[2]), "+f"(d[3])
        : "r"(a[0]), "r"(a[1]), "r"(a[2]), "r"(a[3]), "r"(b0), "r"(b1));
}

// ---------------------------------------------------------------------------
// bf16-split tensor-core GEMM: C[M,N] = A[M,K] @ W[N,K]^T + bias.
// flags: 1=accum(+=C), 2=gelu. M,N mult of 128; K mult of 32. 256 threads.
// Split: A = Ahi + Alo, W = Bhi + Blo; C ~= AhiBhi + AhiBlo + AloBhi (fp32 acc).
// smem rows strided 40 bf16 (80B) -> ldmatrix row addresses conflict-free.
// ---------------------------------------------------------------------------
__global__ __launch_bounds__(256) void gemm_mma(
    const float* __restrict__ A, const float* __restrict__ W,
    const float* __restrict__ bias, float* __restrict__ C,
    int M, int N, int K, int flags) {
    __shared__ __align__(16) uint32_t smAhi[128 * 20];
    __shared__ __align__(16) uint32_t smAlo[128 * 20];
    __shared__ __align__(16) uint32_t smBhi[128 * 20];
    __shared__ __align__(16) uint32_t smBlo[128 * 20];

    const int tid = threadIdx.x;
    const int wid = tid >> 5, lane = tid & 31;
    const int bm = blockIdx.y * 128, bn = blockIdx.x * 128;
    const int warp_m = (wid & 3) * 32, warp_n = (wid >> 2) * 64;

    const uint32_t bAhi = smem_u32(smAhi), bAlo = smem_u32(smAlo);
    const uint32_t bBhi = smem_u32(smBhi), bBlo = smem_u32(smBlo);

    // ldmatrix lane geometry
    const int mi = lane >> 3, l7 = lane & 7;
    const int a_r8 = (mi & 1) * 8 + l7, a_k8 = (mi >> 1) * 8;       // A matrices
    const int b_r8 = (mi >> 1) * 8 + l7, b_k8 = (mi & 1) * 8;       // B matrices

    // staging geometry: thread handles row r, 16 k-values at kh
    const int sr = tid >> 1, skh = (tid & 1) * 16;
    const uint32_t sidx = (uint32_t)((sr * 40 + skh) >> 1);          // uint32 index

    float acc[2][8][4];
#pragma unroll
    for (int mt = 0; mt < 2; mt++)
#pragma unroll
        for (int nt = 0; nt < 8; nt++)
#pragma unroll
            for (int c = 0; c < 4; c++) acc[mt][nt][c] = 0.f;

    const int nch = K >> 5;
    for (int ch = 0; ch < nch; ch++) {
        const int kb = ch << 5;
        // ---- stage + split convert
        {
            const float* ap = A + (size_t)(bm + sr) * K + kb + skh;
            const float* bp = W + (size_t)(bn + sr) * K + kb + skh;
#pragma unroll
            for (int j = 0; j < 4; j++) {
                const float4 va = *(const float4*)(ap + j * 4);
                const float4 vb = *(const float4*)(bp + j * 4);
                float af[4] = {va.x, va.y, va.z, va.w};
                float bf[4] = {vb.x, vb.y, vb.z, vb.w};
                uint32_t ah[2], al[2], bh[2], bl[2];
#pragma unroll
                for (int p = 0; p < 2; p++) {
                    __nv_bfloat16 h0 = __float2bfloat16(af[p * 2]);
                    __nv_bfloat16 h1 = __float2bfloat16(af[p * 2 + 1]);
                    __nv_bfloat16 q0 = __float2bfloat16(af[p * 2] - __bfloat162float(h0));
                    __nv_bfloat16 q1 = __float2bfloat16(af[p * 2 + 1] - __bfloat162float(h1));
                    __nv_bfloat162 ph(h0, h1), pl(q0, q1);
                    ah[p] = *(uint32_t*)&ph; al[p] = *(uint32_t*)&pl;
                    h0 = __float2bfloat16(bf[p * 2]);
                    h1 = __float2bfloat16(bf[p * 2 + 1]);
                    q0 = __float2bfloat16(bf[p * 2] - __bfloat162float(h0));
                    q1 = __float2bfloat16(bf[p * 2 + 1] - __bfloat162float(h1));
                    __nv_bfloat162 rh(h0, h1), rl(q0, q1);
                    bh[p] = *(uint32_t*)&rh; bl[p] = *(uint32_t*)&rl;
                }
                smAhi[sidx + j * 2 + 0] = ah[0]; smAhi[sidx + j * 2 + 1] = ah[1];
                smAlo[sidx + j * 2 + 0] = al[0]; smAlo[sidx + j * 2 + 1] = al[1];
                smBhi[sidx + j * 2 + 0] = bh[0]; smBhi[sidx + j * 2 + 1] = bh[1];
                smBlo[sidx + j * 2 + 0] = bl[0]; smBlo[sidx + j * 2 + 1] = bl[1];
            }
        }
        __syncthreads();
        // ---- compute
#pragma unroll
        for (int ks = 0; ks < 2; ks++) {
            const int k0 = ks * 16;
            uint32_t aHi[2][4], aLo[2][4];
#pragma unroll
            for (int mt = 0; mt < 2; mt++) {
                const uint32_t off =
                    (uint32_t)(((warp_m + mt * 16 + a_r8) * 40 + k0 + a_k8) * 2);
                ldsm_x4(aHi[mt][0], aHi[mt][1], aHi[mt][2], aHi[mt][3], bAhi + off);
                ldsm_x4(aLo[mt][0], aLo[mt][1], aLo[mt][2], aLo[mt][3], bAlo + off);
            }
#pragma unroll
            for (int np = 0; np < 4; np++) {
                const uint32_t off =
                    (uint32_t)(((warp_n + np * 16 + b_r8) * 40 + k0 + b_k8) * 2);
                uint32_t h0, h1, h2, h3, l0, l1, l2, l3;
                ldsm_x4(h0, h1, h2, h3, bBhi + off);
                ldsm_x4(l0, l1, l2, l3, bBlo + off);
#pragma unroll
                for (int mt = 0; mt < 2; mt++) {
                    mma_bf16(acc[mt][np * 2 + 0], aHi[mt], h0, h1);
                    mma_bf16(acc[mt][np * 2 + 0], aLo[mt], h0, h1);
                    mma_bf16(acc[mt][np * 2 + 0], aHi[mt], l0, l1);
                    mma_bf16(acc[mt][np * 2 + 1], aHi[mt], h2, h3);
                    mma_bf16(acc[mt][np * 2 + 1], aLo[mt], h2, h3);
                    mma_bf16(acc[mt][np * 2 + 1], aHi[mt], l2, l3);
                }
            }
        }
        __syncthreads();
    }

    // ---- epilogue: fragment layout c0,c1 -> (row g, col 2t..2t+1); c2,c3 -> row g+8
    const int g = lane >> 2, tg = lane & 3;
#pragma unroll
    for (int mt = 0; mt < 2; mt++) {
#pragma unroll
        for (int nt = 0; nt < 8; nt++) {
            const int col = bn + warp_n + nt * 8 + tg * 2;
            const float b0 = bias[col], b1 = bias[col + 1];
#pragma unroll
            for (int h = 0; h < 2; h++) {
                const int row = bm + warp_m + mt * 16 + g + h * 8;
                float v0 = acc[mt][nt][h * 2 + 0] + b0;
                float v1 = acc[mt][nt][h * 2 + 1] + b1;
                if (flags & 2) {
                    v0 = 0.5f * v0 * (1.0f + erff(v0 * 0.70710678118654752f));
                    v1 = 0.5f * v1 * (1.0f + erff(v1 * 0.70710678118654752f));
                }
                float* cp = C + (size_t)row * N + col;
                if (flags & 1) { v0 += cp[0]; v1 += cp[1]; }
                *(float2*)cp = make_float2(v0, v1);
            }
        }
    }
}

// ---------------------------------------------------------------------------
// Elementwise / small kernels
// ---------------------------------------------------------------------------
__global__ void copy4_k(float* __restrict__ dst, const float* __restrict__ src, size_t n4) {
    size_t i = (size_t)blockIdx.x * blockDim.x + threadIdx.x;
    size_t st = (size_t)gridDim.x * blockDim.x;
    for (; i < n4; i += st) ((float4*)dst)[i] = ((const float4*)src)[i];
}

__global__ void fill_k(float* __restrict__ dst, size_t n, float v) {
    size_t i = (size_t)blockIdx.x * blockDim.x + threadIdx.x;
    size_t st = (size_t)gridDim.x * blockDim.x;
    for (; i < n; i += st) dst[i] = v;
}

__global__ void axpyg_k(float* __restrict__ dst, const float* __restrict__ src,
                        const float* __restrict__ g, size_t n) {
    size_t i = (size_t)blockIdx.x * blockDim.x + threadIdx.x;
    size_t st = (size_t)gridDim.x * blockDim.x;
    for (; i < n; i += st) dst[i] = fmaf(g[i & (D_ - 1)], src[i], dst[i]);
}

__global__ void concat_k(float* __restrict__ comb, const float* __restrict__ q,
                         const float* __restrict__ ins) {
    size_t n = SM;
    size_t i = (size_t)blockIdx.x * blockDim.x + threadIdx.x;
    size_t st = (size_t)gridDim.x * blockDim.x;
    for (; i < n; i += st) {
        int b = (int)(i / (128 * D_));
        int rem = (int)(i % (128 * D_));
        int t = rem / D_, d = rem % D_;
        comb[i] = (t < QN) ? q[((size_t)b * QN + t) * D_ + d]
                           : ins[((size_t)b * IN_ + (t - QN)) * D_ + d];
    }
}

__global__ void slice_k(float* __restrict__ qry, const float* __restrict__ comb) {
    size_t n = (size_t)B_ * QN * D_;
    size_t i = (size_t)blockIdx.x * blockDim.x + threadIdx.x;
    size_t st = (size_t)gridDim.x * blockDim.x;
    for (; i < n; i += st) {
        int b = (int)(i / (QN * D_));
        int rem = (int)(i % (QN * D_));
        qry[i] = comb[(size_t)b * 128 * D_ + rem];
    }
}

// d_out is FLOAT32; reference is bf16-quantized -> emit bf16-rounded fp32.
__global__ void out_f32_k(float* __restrict__ out, const float* __restrict__ x, size_t n) {
    size_t i = (size_t)blockIdx.x * blockDim.x + threadIdx.x;
    size_t st = (size_t)gridDim.x * blockDim.x;
    for (; i < n; i += st) out[i] = __bfloat162float(__float2bfloat16(x[i]));
}

__global__ void add_pos_k(float* __restrict__ ctx, const int* __restrict__ coords,
                          const float* __restrict__ pe) {
    const int bl = blockIdx.x, tid = threadIdx.x;
    const int c0 = coords[bl * 2]     / 256;
    const int c1 = coords[bl * 2 + 1] / 256;
    const size_t pidx = (size_t)(c0 * 256 + c1) * D_;
    float4* dst = (float4*)(ctx + (size_t)bl * D_);
    const float4* src = (const float4*)(pe + pidx);
    float4 a = dst[tid], b = src[tid];
    a.x += b.x; a.y += b.y; a.z += b.z; a.w += b.w;
    dst[tid] = a;
}

// ---------------------------------------------------------------------------
// LayerNorm
// ---------------------------------------------------------------------------
__global__ __launch_bounds__(128) void layernorm_k(
    const float* __restrict__ x, float* __restrict__ y,
    const float* __restrict__ g, const float* __restrict__ bet) {
    const int row = blockIdx.x, tid = threadIdx.x;
    const float4 v = ((const float4*)(x + (size_t)row * D_))[tid];
    float s = v.x + v.y + v.z + v.w;
    float sq = v.x * v.x + v.y * v.y + v.z * v.z + v.w * v.w;
#pragma unroll
    for (int o = 16; o > 0; o >>= 1) {
        s  += __shfl_xor_sync(0xffffffffu, s, o);
        sq += __shfl_xor_sync(0xffffffffu, sq, o);
    }
    __shared__ float sh[8];
    if ((tid & 31) == 0) { sh[tid >> 5] = s; sh[4 + (tid >> 5)] = sq; }
    __syncthreads();
    s  = sh[0] + sh[1] + sh[2] + sh[3];
    sq = sh[4] + sh[5] + sh[6] + sh[7];
    const float mean = s * (1.0f / D_);
    const float var  = sq * (1.0f / D_) - mean * mean;
    const float rs = rsqrtf(var + 1e-5f);
    const float4 gv = ((const float4*)g)[tid];
    const float4 bv = ((const float4*)bet)[tid];
    float4 o;
    o.x = (v.x - mean) * rs * gv.x + bv.x;
    o.y = (v.y - mean) * rs * gv.y + bv.y;
    o.z = (v.z - mean) * rs * gv.z + bv.z;
    o.w = (v.w - mean) * rs * gv.w + bv.w;
    ((float4*)(y + (size_t)row * D_))[tid] = o;
}

// ---------------------------------------------------------------------------
// SGEMM (NT) fallback for small M
// ---------------------------------------------------------------------------
__global__ __launch_bounds__(256) void gemm_nt(
    const float* __restrict__ A, const float* __restrict__ W,
    const float* __restrict__ bias, float* __restrict__ C,
    int M, int N, int K, int flags) {
    __shared__ float As[16 * 136];
    __shared__ float Bs[16 * 136];
    const int tid = threadIdx.x;
    const int bm = blockIdx.y * 128, bn = blockIdx.x * 128;
    const int tr = (tid & 15) * 8;
    const int tc = (tid >> 4) * 8;
    const int lr0 = tid >> 1;
    const int lk0 = (tid & 1) * 8;
    float acc[8][8];
#pragma unroll
    for (int x = 0; x < 8; x++)
#pragma unroll
        for (int y = 0; y < 8; y++) acc[x][y] = 0.f;

    for (int k0 = 0; k0 < K; k0 += 16) {
        {
            const int r = bm + lr0;
            float4 a0, a1;
            if (r < M) {
                const float* src = A + (size_t)r * K + k0 + lk0;
                a0 = *(const float4*)src; a1 = *(const float4*)(src + 4);
            } else {
                a0 = make_float4(0, 0, 0, 0); a1 = a0;
            }
            As[(lk0 + 0) * 136 + lr0] = a0.x; As[(lk0 + 1) * 136 + lr0] = a0.y;
            As[(lk0 + 2) * 136 + lr0] = a0.z; As[(lk0 + 3) * 136 + lr0] = a0.w;
            As[(lk0 + 4) * 136 + lr0] = a1.x; As[(lk0 + 5) * 136 + lr0] = a1.y;
            As[(lk0 + 6) * 136 + lr0] = a1.z; As[(lk0 + 7) * 136 + lr0] = a1.w;
            const float* srcb = W + (size_t)(bn + lr0) * K + k0 + lk0;
            float4 b0 = *(const float4*)srcb; float4 b1 = *(const float4*)(srcb + 4);
            Bs[(lk0 + 0) * 136 + lr0] = b0.x; Bs[(lk0 + 1) * 136 + lr0] = b0.y;
            Bs[(lk0 + 2) * 136 + lr0] = b0.z; Bs[(lk0 + 3) * 136 + lr0] = b0.w;
            Bs[(lk0 + 4) * 136 + lr0] = b1.x; Bs[(lk0 + 5) * 136 + lr0] = b1.y;
            Bs[(lk0 + 6) * 136 + lr0] = b1.z; Bs[(lk0 + 7) * 136 + lr0] = b1.w;
        }
        __syncthreads();
#pragma unroll
        for (int kk = 0; kk < 16; kk++) {
            const float* ar = As + kk * 136 + tr;
            const float* br = Bs + kk * 136 + tc;
            float4 a0 = *(const float4*)ar, a1 = *(const float4*)(ar + 4);
            float4 b0 = *(const float4*)br, b1 = *(const float4*)(br + 4);
            float ra[8] = {a0.x, a0.y, a0.z, a0.w, a1.x, a1.y, a1.z, a1.w};
            float rb[8] = {b0.x, b0.y, b0.z, b0.w, b1.x, b1.y, b1.z, b1.w};
#pragma unroll
            for (int x = 0; x < 8; x++)
#pragma unroll
                for (int y = 0; y < 8; y++)
                    acc[x][y] = fmaf(ra[x], rb[y], acc[x][y]);
        }
        __syncthreads();
    }
#pragma unroll
    for (int x = 0; x < 8; x++) {
        const int r = bm + tr + x;
        if (r >= M) break;
        float* crow = C + (size_t)r * N + bn + tc;
#pragma unroll
        for (int y = 0; y < 8; y++) {
            float c = acc[x][y] + bias[bn + tc + y];
            if (flags & 2) c = 0.5f * c * (1.0f + erff(c * 0.70710678118654752f));
            if (flags & 1) c += crow[y];
            crow[y] = c;
        }
    }
}

// ---------------------------------------------------------------------------
// Flash dilated-attention branch
// ---------------------------------------------------------------------------
__global__ __launch_bounds__(128) void dil_branch_k(
    const float* __restrict__ Qm, const float* __restrict__ Km, const float* __restrict__ Vm,
    float* __restrict__ ofb, float* __restrict__ lfb, int w, int r) {
    __shared__ float Ks[32 * 64];
    __shared__ float Vs[32 * 64];
    __shared__ float Ss[32 * 128];
    const int nseg = L_ / w;
    int t = blockIdx.x;
    const int qt = t & 3; t >>= 2;
    const int h = t & 7; t >>= 3;
    const int seg = t % nseg; const int b = t / nseg;
    const int base = seg * w + (h & (r - 1));
    const int tid = threadIdx.x;
    const int j = qt * 128 + tid;
    const size_t rowq = (size_t)b * L_ + base + (size_t)r * j;
    const float* qp = Qm + rowq * D_ + h * DH_;
    float q[64];
#pragma unroll
    for (int d = 0; d < 64; d += 4) {
        float4 tv = *(const float4*)(qp + d);
        q[d] = tv.x; q[d + 1] = tv.y; q[d + 2] = tv.z; q[d + 3] = tv.w;
    }
    float o[64];
#pragma unroll
    for (int d = 0; d < 64; d++) o[d] = 0.f;
    float mv = -INFINITY, ls = 0.f;

    for (int kt = 0; kt < 16; kt++) {
        __syncthreads();
        for (int li = tid; li < 512; li += 128) {
            const int kk = li >> 4, dq = (li & 15) << 2;
            const size_t gp = ((size_t)b * L_ + base + (size_t)r * (kt * 32 + kk)) * D_
                              + h * DH_ + dq;
            *(float4*)(Ks + kk * 64 + dq) = *(const float4*)(Km + gp);
            *(float4*)(Vs + kk * 64 + dq) = *(const float4*)(Vm + gp);
        }
        __syncthreads();
        float tmax = -INFINITY;
#pragma unroll 1
        for (int kk = 0; kk < 32; kk++) {
            const float* kr = Ks + kk * 64;
            float s = 0.f;
#pragma unroll
            for (int d = 0; d < 64; d += 4) {
                float4 kv = *(const float4*)(kr + d);
                s = fmaf(q[d], kv.x, s);     s = fmaf(q[d + 1], kv.y, s);
                s = fmaf(q[d + 2], kv.z, s); s = fmaf(q[d + 3], kv.w, s);
            }
            s *= SCALE_;
            Ss[kk * 128 + tid] = s;
            tmax = fmaxf(tmax, s);
        }
        const float mn = fmaxf(mv, tmax);
        const float corr = __expf(mv - mn);
        ls *= corr;
#pragma unroll
        for (int d = 0; d < 64; d++) o[d] *= corr;
#pragma unroll 1
        for (int kk = 0; kk < 32; kk++) {
            const float p = __expf(Ss[kk * 128 + tid] - mn);
            ls += p;
            const float* vr = Vs + kk * 64;
#pragma unroll
            for (int d = 0; d < 64; d += 4) {
                float4 vv = *(const float4*)(vr + d);
                o[d]     = fmaf(p, vv.x, o[d]);
                o[d + 1] = fmaf(p, vv.y, o[d + 1]);
                o[d + 2] = fmaf(p, vv.z, o[d + 2]);
                o[d + 3] = fmaf(p, vv.w, o[d + 3]);
            }
        }
        mv = mn;
    }
    const float inv = 1.0f / ls;
    float* op = ofb + rowq * D_ + h * DH_;
#pragma unroll
    for (int d = 0; d < 64; d += 4) {
        float4 tv = make_float4(o[d] * inv, o[d + 1] * inv, o[d + 2] * inv, o[d + 3] * inv);
        *(float4*)(op + d) = tv;
    }
    lfb[rowq * H_ + h] = mv + logf(ls);
}

// ---------------------------------------------------------------------------
// Flash generic attention partial (split-KV)
// ---------------------------------------------------------------------------
__global__ __launch_bounds__(128) void attn_part_k(
    const float* __restrict__ Qm, const float* __restrict__ Km, const float* __restrict__ Vm,
    float* __restrict__ op_, float* __restrict__ lse_,
    int Tq, int Tk, int chunk) {
    __shared__ float Ks[32 * 64];
    __shared__ float Vs[32 * 64];
    __shared__ float Ss[32 * 128];
    const int split = blockIdx.x;
    const int b = blockIdx.y >> 3;
    const int h = blockIdx.y & 7;
    const int qt = blockIdx.z;
    const int tid = threadIdx.x;
    const int qi = qt * 128 + tid;
    const bool act = qi < Tq;
    const float* qp = Qm + ((size_t)b * Tq + (act ? qi : 0)) * D_ + h * DH_;
    float q[64];
#pragma unroll
    for (int d = 0; d < 64; d += 4) {
        float4 tv = *(const float4*)(qp + d);
        q[d] = tv.x; q[d + 1] = tv.y; q[d + 2] = tv.z; q[d + 3] = tv.w;
    }
    float o[64];
#pragma unroll
    for (int d = 0; d < 64; d++) o[d] = 0.f;
    float mv = -INFINITY, ls = 0.f;
    const int k0 = split * chunk;
    const int ntile = chunk / 32;

    for (int kt = 0; kt < ntile; kt++) {
        __syncthreads();
        for (int li = tid; li < 512; li += 128) {
            const int kk = li >> 4, dq = (li & 15) << 2;
            const size_t gp = ((size_t)b * Tk + k0 + kt * 32 + kk) * D_ + h * DH_ + dq;
            *(float4*)(Ks + kk * 64 + dq) = *(const float4*)(Km + gp);
            *(float4*)(Vs + kk * 64 + dq) = *(const float4*)(Vm + gp);
        }
        __syncthreads();
        float tmax = -INFINITY;
#pragma unroll 1
        for (int kk = 0; kk < 32; kk++) {
            const float* kr = Ks + kk * 64;
            float s = 0.f;
#pragma unroll
            for (int d = 0; d < 64; d += 4) {
                float4 kv = *(const float4*)(kr + d);
                s = fmaf(q[d], kv.x, s);     s = fmaf(q[d + 1], kv.y, s);
                s = fmaf(q[d + 2], kv.z, s); s = fmaf(q[d + 3], kv.w, s);
            }
            s *= SCALE_;
            Ss[kk * 128 + tid] = s;
            tmax = fmaxf(tmax, s);
        }
        const float mn = fmaxf(mv, tmax);
        const float corr = __expf(mv - mn);
        ls *= corr;
#pragma unroll
        for (int d = 0; d < 64; d++) o[d] *= corr;
#pragma unroll 1
        for (int kk = 0; kk < 32; kk++) {
            const float p = __expf(Ss[kk * 128 + tid] - mn);
            ls += p;
            const float* vr = Vs + kk * 64;
#pragma unroll
            for (int d = 0; d < 64; d += 4) {
                float4 vv = *(const float4*)(vr + d);
                o[d]     = fmaf(p, vv.x, o[d]);
                o[d + 1] = fmaf(p, vv.y, o[d + 1]);
                o[d + 2] = fmaf(p, vv.z, o[d + 2]);
                o[d + 3] = fmaf(p, vv.w, o[d + 3]);
            }
        }
        mv = mn;
    }
    if (act) {
        const size_t RH = (size_t)B_ * Tq * H_;
        const size_t idx = (size_t)split * RH + ((size_t)b * Tq + qi) * H_ + h;
        const float inv = 1.0f / ls;
        float* op = op_ + idx * 64;
#pragma unroll
        for (int d = 0; d < 64; d += 4) {
            float4 tv = make_float4(o[d] * inv, o[d + 1] * inv, o[d + 2] * inv, o[d + 3] * inv);
            *(float4*)(op + d) = tv;
        }
        lse_[idx] = mv + logf(ls);
    }
}

// ---------------------------------------------------------------------------
// LSE-weighted combine
// ---------------------------------------------------------------------------
__global__ __launch_bounds__(64) void combine_k(
    const float* __restrict__ op, const float* __restrict__ lse,
    float* __restrict__ out, int ns, size_t RH) {
    const size_t i = blockIdx.x;
    const int tid = threadIdx.x;
    float m = -INFINITY;
    for (int s = 0; s < ns; s++) {
        const float l = lse[(size_t)s * RH + i];
        if (l > -1e8f) m = fmaxf(m, l);
    }
    float tot = 0.f, acc = 0.f;
    for (int s = 0; s < ns; s++) {
        const float l = lse[(size_t)s * RH + i];
        if (l > -1e8f) {
            const float w = __expf(l - m);
            tot += w;
            acc = fmaf(w, op[((size_t)s * RH + i) * 64 + tid], acc);
        }
    }
    out[i * 64 + tid] = acc / tot;
}

// ---------------------------------------------------------------------------
// Host orchestration
// ---------------------------------------------------------------------------
static inline void gemm(const float* A, const float* W, const float* bias, float* C,
                        int M, int N, int K, int flags) {
    if ((M & 127) == 0 && M >= 1024) {
        dim3 g(N / 128, M / 128);
        gemm_mma<<<g, 256>>>(A, W, bias, C, M, N, K, flags);
    } else {
        dim3 g(N / 128, (M + 127) / 128);
        gemm_nt<<<g, 256>>>(A, W, bias, C, M, N, K, flags);
    }
}

extern "C" void kernel_launch(void* const* d_in, const int* in_sizes, int n_in,
                              void* d_out, int out_size) {
    (void)in_sizes; (void)n_in; (void)out_size;
    const float* querys   = (const float*)d_in[0];
    const float* contexts = (const float*)d_in[1];
    const float* instr    = (const float*)d_in[2];
    const int*   coords   = (const int*)d_in[3];
    const float* pe       = (const float*)d_in[4];
    const float* qkv_w    = (const float*)d_in[5];
    const float* qkv_b    = (const float*)d_in[6];
    const float* ln_ln    = (const float*)d_in[7];
    const float* fc1_w    = (const float*)d_in[8];
    const float* fc1_b    = (const float*)d_in[9];
    const float* fc2_w    = (const float*)d_in[10];
    const float* fc2_b    = (const float*)d_in[11];
    const float* ln_fin   = (const float*)d_in[12];
    const float* sa_w     = (const float*)d_in[13];
    const float* sa_b     = (const float*)d_in[14];
    const float* sa_ln    = (const float*)d_in[15];
    const float* sa_g     = (const float*)d_in[16];
    const float* sa_f1w   = (const float*)d_in[17];
    const float* sa_f1b   = (const float*)d_in[18];
    const float* sa_f2w   = (const float*)d_in[19];
    const float* sa_f2b   = (const float*)d_in[20];
    const float* ca_w     = (const float*)d_in[21];
    const float* ca_b     = (const float*)d_in[22];
    const float* ca_ln    = (const float*)d_in[23];

    float* g;
    { void* p = nullptr; cudaGetSymbolAddress(&p, gbuf); g = (float*)p; }
    float *X = g + OFF_X, *Hb = g + OFF_H, *Qb = g + OFF_Q, *Kb = g + OFF_K,
          *Vb = g + OFF_V, *OC = g + OFF_OC, *CTX = g + OFF_CTX, *O5 = g + OFF_O5,
          *FFb = g + OFF_FF, *LSE5 = g + OFF_LSE5, *COMB = g + OFF_COMB,
          *HS = g + OFF_HS, *OS = g + OFF_OS, *Tt = g + OFF_T, *FFS = g + OFF_FFS,
          *QRY = g + OFF_QRY, *PART = g + OFF_PART, *PLSE = g + OFF_PLSE;

    copy4_k<<<4096, 256>>>(CTX, contexts, S_ / 4);
    add_pos_k<<<B_ * L_, 128>>>(CTX, coords, pe);
    copy4_k<<<64, 256>>>(QRY, querys, (size_t)B_ * QN * D_ / 4);

    const int WS[5] = {512, 1024, 2048, 4096, 8192};
    const int RS[5] = {1, 2, 4, 8, 16};

    for (int i = 0; i < 2; i++) {
        copy4_k<<<4096, 256>>>(X, CTX, S_ / 4);
        for (int j = 0; j < 2; j++) {
            const int ij = i * 2 + j;
            const float* lg0 = ln_ln + (size_t)((ij * 2 + 0) * 2) * D_;
            layernorm_k<<<B_ * L_, 128>>>(X, Hb, lg0, lg0 + D_);
            const float* Wq = qkv_w + (size_t)(ij * 4) * DD;
            const float* bq = qkv_b + (size_t)(ij * 4) * D_;
            gemm(Hb, Wq,          bq,          Qb, B_ * L_, D_, D_, 0);
            gemm(Hb, Wq + DD,     bq + D_,     Kb, B_ * L_, D_, D_, 0);
            gemm(Hb, Wq + 2 * DD, bq + 2 * D_, Vb, B_ * L_, D_, D_, 0);
            fill_k<<<2560, 256>>>(LSE5, 5 * BLH, NEGV);
            for (int br = 0; br < 5; br++) {
                const int w = WS[br], r = RS[br], nseg = L_ / w;
                dil_branch_k<<<B_ * nseg * H_ * 4, 128>>>(
                    Qb, Kb, Vb, O5 + (size_t)br * S_, LSE5 + (size_t)br * BLH, w, r);
            }
            combine_k<<<(unsigned)BLH, 64>>>(O5, LSE5, OC, 5, BLH);
            gemm(OC, Wq + 3 * DD, bq + 3 * D_, X, B_ * L_, D_, D_, 1);
            const float* lg1 = ln_ln + (size_t)((ij * 2 + 1) * 2) * D_;
            layernorm_k<<<B_ * L_, 128>>>(X, Hb, lg1, lg1 + D_);
            gemm(Hb, fc1_w + (size_t)ij * FF_ * D_, fc1_b + (size_t)ij * FF_,
                 FFb, B_ * L_, FF_, D_, 2);
            gemm(FFb, fc2_w + (size_t)ij * D_ * FF_, fc2_b + (size_t)ij * D_,
                 X, B_ * L_, D_, FF_, 1);
        }
        layernorm_k<<<B_ * L_, 128>>>(X, CTX, ln_fin + (size_t)i * 2 * D_,
                                      ln_fin + (size_t)i * 2 * D_ + D_);
        concat_k<<<512, 256>>>(COMB, QRY, instr);
        const float* sl0 = sa_ln + (size_t)((i * 2 + 0) * 2) * D_;
        layernorm_k<<<B_ * 128, 128>>>(COMB, HS, sl0, sl0 + D_);
        const float* Ws = sa_w + (size_t)i * 4 * DD;
        const float* bs = sa_b + (size_t)i * 4 * D_;
        gemm(HS, Ws,          bs,          Qb, B_ * 128, D_, D_, 0);
        gemm(HS, Ws + DD,     bs + D_,     Kb, B_ * 128, D_, D_, 0);
        gemm(HS, Ws + 2 * DD, bs + 2 * D_, Vb, B_ * 128, D_, D_, 0);
        attn_part_k<<<dim3(1, B_ * H_, 1), 128>>>(Qb, Kb, Vb, PART, PLSE, 128, 128, 128);
        combine_k<<<B_ * 128 * H_, 64>>>(PART, PLSE, OS, 1, (size_t)B_ * 128 * H_);
        gemm(OS, Ws + 3 * DD, bs + 3 * D_, Tt, B_ * 128, D_, D_, 0);
        axpyg_k<<<128, 256>>>(COMB, Tt, sa_g + (size_t)(i * 2 + 0) * D_, SM);
        const float* sl1 = sa_ln + (size_t)((i * 2 + 1) * 2) * D_;
        layernorm_k<<<B_ * 128, 128>>>(COMB, HS, sl1, sl1 + D_);
        gemm(HS, sa_f1w + (size_t)i * FF_ * D_, sa_f1b + (size_t)i * FF_,
             FFS, B_ * 128, FF_, D_, 2);
        gemm(FFS, sa_f2w + (size_t)i * D_ * FF_, sa_f2b + (size_t)i * D_,
             Tt, B_ * 128, D_, FF_, 0);
        axpyg_k<<<128, 256>>>(COMB, Tt, sa_g + (size_t)(i * 2 + 1) * D_, SM);
        slice_k<<<32, 256>>>(QRY, COMB);
        const float* Wc = ca_w + (size_t)i * 4 * DD;
        const float* bc = ca_b + (size_t)i * 4 * D_;
        gemm(QRY, Wc,          bc,          Qb, B_ * QN, D_, D_, 0);
        gemm(CTX, Wc + DD,     bc + D_,     Kb, B_ * L_, D_, D_, 0);
        gemm(CTX, Wc + 2 * DD, bc + 2 * D_, Vb, B_ * L_, D_, D_, 0);
        attn_part_k<<<dim3(32, B_ * H_, 1), 128>>>(Qb, Kb, Vb, PART, PLSE, QN, L_, 256);
        combine_k<<<B_ * QN * H_, 64>>>(PART, PLSE, OS, 32, (size_t)B_ * QN * H_);
        gemm(OS, Wc + 3 * DD, bc + 3 * D_, QRY, B_ * QN, D_, D_, 1);
        layernorm_k<<<B_ * QN, 128>>>(QRY, QRY, ca_ln + (size_t)i * 2 * D_,
                                      ca_ln + (size_t)i * 2 * D_ + D_);
    }
    out_f32_k<<<32, 256>>>((float*)d_out, QRY, (size_t)B_ * QN * D_);
}

// round 13
// speedup vs baseline: 1.5087x; 1.1458x over previous
#include <cuda_runtime.h>
#include <cuda_bf16.h>
#include <math.h>
#include <stdint.h>

// ---------------------------------------------------------------------------
// Problem constants
// ---------------------------------------------------------------------------
#define B_   2
#define L_   8192
#define QN   32
#define IN_  96
#define D_   512
#define H_   8
#define DH_  64
#define FF_  2048
#define SCALE_ 0.125f
#define NEGV  (-1.0e9f)

constexpr size_t S_  = (size_t)B_ * L_ * D_;
constexpr size_t BLH = (size_t)B_ * L_ * H_;
constexpr size_t SM  = (size_t)B_ * 128 * D_;
constexpr size_t DD  = (size_t)D_ * D_;

constexpr size_t OFF_X    = 0;
constexpr size_t OFF_H    = S_;
constexpr size_t OFF_Q    = 2 * S_;
constexpr size_t OFF_K    = 3 * S_;
constexpr size_t OFF_V    = 4 * S_;
constexpr size_t OFF_OC   = 5 * S_;
constexpr size_t OFF_CTX  = 6 * S_;
constexpr size_t OFF_O5   = 7 * S_;
constexpr size_t OFF_FF   = 12 * S_;
constexpr size_t OFF_LSE5 = 16 * S_;
constexpr size_t OFF_COMB = OFF_LSE5 + 5 * BLH;
constexpr size_t OFF_HS   = OFF_COMB + SM;
constexpr size_t OFF_OS   = OFF_HS + SM;
constexpr size_t OFF_T    = OFF_OS + SM;
constexpr size_t OFF_FFS  = OFF_T + SM;
constexpr size_t OFF_QRY  = OFF_FFS + (size_t)B_ * 128 * FF_;
constexpr size_t OFF_PART = OFF_QRY + (size_t)B_ * QN * D_;
constexpr size_t OFF_PLSE = OFF_PART + (size_t)32 * B_ * QN * H_ * DH_;
constexpr size_t TOTAL_F  = OFF_PLSE + (size_t)32 * B_ * QN * H_;

__device__ float gbuf[TOTAL_F];

// bf16 split scratch: A planes sized for the largest activation matrix
// (16384 x 2048), W planes for the largest weight (2048 x 512).
constexpr size_t AMAX = (size_t)16384 * 2048;
constexpr size_t WMAX = (size_t)2048 * 512;
__device__ __nv_bfloat16 g_ahi[AMAX];
__device__ __nv_bfloat16 g_alo[AMAX];
__device__ __nv_bfloat16 g_whi[WMAX];
__device__ __nv_bfloat16 g_wlo[WMAX];

// ---------------------------------------------------------------------------
// PTX helpers (baseline PTX only; no arch-'a' features)
// ---------------------------------------------------------------------------
__device__ __forceinline__ uint32_t smem_u32(const void* p) {
    uint32_t a;
    asm("{ .reg .u64 t; cvta.to.shared.u64 t, %1; cvt.u32.u64 %0, t; }" : "=r"(a) : "l"(p));
    return a;
}
__device__ __forceinline__ void ldsm_x4(uint32_t& r0, uint32_t& r1, uint32_t& r2,
                                        uint32_t& r3, uint32_t addr) {
    asm volatile("ldmatrix.sync.aligned.m8n8.x4.shared.b16 {%0,%1,%2,%3}, [%4];"
                 : "=r"(r0), "=r"(r1), "=r"(r2), "=r"(r3) : "r"(addr));
}
__device__ __forceinline__ void mma_bf16(float* d, const uint32_t* a, uint32_t b0, uint32_t b1) {
    asm volatile(
        "mma.sync.aligned.m16n8k16.row.col.f32.bf16.bf16.f32 "
        "{%0,%1,%2,%3}, {%4,%5,%6,%7}, {%8,%9}, {%0,%1,%2,%3};"
        : "+f"(d[0]), "+f"(d[1]), "+f"(d[2]), "+f"(d[3])
        : "r"(a[0]), "r"(a[1]), "r"(a[2]), "r"(a[3]), "r"(b0), "r"(b1));
}
#define CP_ASYNC16(dst, src) \
    asm volatile("cp.async.cg.shared.global [%0], [%1], 16;" :: "r"(dst), "l"(src))
#define CP_COMMIT() asm volatile("cp.async.commit_group;" ::: "memory")

// ---------------------------------------------------------------------------
// fp32 -> (bf16 hi, bf16 residual) split, vectorized by 4. n4 = n/4.
// ---------------------------------------------------------------------------
__global__ void split_k(const float* __restrict__ x, __nv_bfloat16* __restrict__ hi,
                        __nv_bfloat16* __restrict__ lo, size_t n4) {
    size_t i = (size_t)blockIdx.x * blockDim.x + threadIdx.x;
    size_t st = (size_t)gridDim.x * blockDim.x;
    for (; i < n4; i += st) {
        const float4 v = ((const float4*)x)[i];
        __nv_bfloat16 h0 = __float2bfloat16(v.x), h1 = __float2bfloat16(v.y);
        __nv_bfloat16 h2 = __float2bfloat16(v.z), h3 = __float2bfloat16(v.w);
        __nv_bfloat16 l0 = __float2bfloat16(v.x - __bfloat162float(h0));
        __nv_bfloat16 l1 = __float2bfloat16(v.y - __bfloat162float(h1));
        __nv_bfloat16 l2 = __float2bfloat16(v.z - __bfloat162float(h2));
        __nv_bfloat16 l3 = __float2bfloat16(v.w - __bfloat162float(h3));
        __nv_bfloat162 ph0(h0, h1), ph1(h2, h3), pl0(l0, l1), pl1(l2, l3);
        uint2 uh, ul;
        uh.x = *(uint32_t*)&ph0; uh.y = *(uint32_t*)&ph1;
        ul.x = *(uint32_t*)&pl0; ul.y = *(uint32_t*)&pl1;
        ((uint2*)hi)[i] = uh;
        ((uint2*)lo)[i] = ul;
    }
}

// ---------------------------------------------------------------------------
// bf16-split tensor-core GEMM, pre-split inputs, cp.async double-buffered.
// C[M,N] = A @ W^T + bias; flags 1=accum, 2=gelu. M,N mult 128, K mult 32.
// smem: 2 stages x 4 tiles (Ahi,Alo,Whi,Wlo), tile = 128 rows x 40 bf16 (80B),
// 10240 B each -> 81920 B dynamic.
// ---------------------------------------------------------------------------
#define GM2_SMEM 81920

__device__ __forceinline__ void stage_load(
    uint32_t sbase, int stage, int ch,
    const __nv_bfloat16* Ahi, const __nv_bfloat16* Alo,
    const __nv_bfloat16* Whi, const __nv_bfloat16* Wlo,
    int bm, int bn, int K, int sr, int ss) {
    const int kb = ch << 5;
    const uint32_t d0 = sbase + stage * 40960 + (uint32_t)(sr * 80 + ss * 16);
    const size_t ao = (size_t)(bm + sr) * K + kb + ss * 8;
    const size_t bo = (size_t)(bn + sr) * K + kb + ss * 8;
    CP_ASYNC16(d0,             Ahi + ao); CP_ASYNC16(d0 + 16,         Ahi + ao + 8);
    CP_ASYNC16(d0 + 10240,     Alo + ao); CP_ASYNC16(d0 + 10240 + 16, Alo + ao + 8);
    CP_ASYNC16(d0 + 20480,     Whi + bo); CP_ASYNC16(d0 + 20480 + 16, Whi + bo + 8);
    CP_ASYNC16(d0 + 30720,     Wlo + bo); CP_ASYNC16(d0 + 30720 + 16, Wlo + bo + 8);
}

__global__ __launch_bounds__(256) void gemm_mma2(
    const __nv_bfloat16* __restrict__ Ahi, const __nv_bfloat16* __restrict__ Alo,
    const __nv_bfloat16* __restrict__ Whi, const __nv_bfloat16* __restrict__ Wlo,
    const float* __restrict__ bias, float* __restrict__ C,
    int M, int N, int K, int flags) {
    extern __shared__ char dsm[];
    const uint32_t sbase = smem_u32(dsm);
    const int tid = threadIdx.x;
    const int wid = tid >> 5, lane = tid & 31;
    const int bm = blockIdx.y * 128, bn = blockIdx.x * 128;
    const int warp_m = (wid & 3) * 32, warp_n = (wid >> 2) * 64;

    const int mi = lane >> 3, l7 = lane & 7;
    const int a_r8 = (mi & 1) * 8 + l7, a_k8 = (mi >> 1) * 8;
    const int b_r8 = (mi >> 1) * 8 + l7, b_k8 = (mi & 1) * 8;

    const int sr = tid >> 1, ss = (tid & 1) * 2;

    float acc[2][8][4];
#pragma unroll
    for (int mt = 0; mt < 2; mt++)
#pragma unroll
        for (int nt = 0; nt < 8; nt++)
#pragma unroll
            for (int c = 0; c < 4; c++) acc[mt][nt][c] = 0.f;

    const int nch = K >> 5;
    stage_load(sbase, 0, 0, Ahi, Alo, Whi, Wlo, bm, bn, K, sr, ss);
    CP_COMMIT();

    for (int ch = 0; ch < nch; ch++) {
        const int cur = ch & 1;
        const bool more = (ch + 1) < nch;
        if (more) {
            stage_load(sbase, cur ^ 1, ch + 1, Ahi, Alo, Whi, Wlo, bm, bn, K, sr, ss);
            CP_COMMIT();
            asm volatile("cp.async.wait_group 1;" ::: "memory");
        } else {
            asm volatile("cp.async.wait_group 0;" ::: "memory");
        }
        __syncthreads();
        const uint32_t tb = sbase + (uint32_t)(cur * 40960);
#pragma unroll
        for (int ks = 0; ks < 2; ks++) {
            const int k0 = ks * 16;
            uint32_t aHi[2][4], aLo[2][4];
#pragma unroll
            for (int mt = 0; mt < 2; mt++) {
                const uint32_t off =
                    (uint32_t)(((warp_m + mt * 16 + a_r8) * 40 + k0 + a_k8) * 2);
                ldsm_x4(aHi[mt][0], aHi[mt][1], aHi[mt][2], aHi[mt][3], tb + off);
                ldsm_x4(aLo[mt][0], aLo[mt][1], aLo[mt][2], aLo[mt][3], tb + 10240 + off);
            }
#pragma unroll
            for (int np = 0; np < 4; np++) {
                const uint32_t off =
                    (uint32_t)(((warp_n + np * 16 + b_r8) * 40 + k0 + b_k8) * 2);
                uint32_t h0, h1, h2, h3, l0, l1, l2, l3;
                ldsm_x4(h0, h1, h2, h3, tb + 20480 + off);
                ldsm_x4(l0, l1, l2, l3, tb + 30720 + off);
#pragma unroll
                for (int mt = 0; mt < 2; mt++) {
                    mma_bf16(acc[mt][np * 2 + 0], aHi[mt], h0, h1);
                    mma_bf16(acc[mt][np * 2 + 0], aLo[mt], h0, h1);
                    mma_bf16(acc[mt][np * 2 + 0], aHi[mt], l0, l1);
                    mma_bf16(acc[mt][np * 2 + 1], aHi[mt], h2, h3);
                    mma_bf16(acc[mt][np * 2 + 1], aLo[mt], h2, h3);
                    mma_bf16(acc[mt][np * 2 + 1], aHi[mt], l2, l3);
                }
            }
        }
        __syncthreads();
    }

    const int g = lane >> 2, tg = lane & 3;
#pragma unroll
    for (int mt = 0; mt < 2; mt++) {
#pragma unroll
        for (int nt = 0; nt < 8; nt++) {
            const int col = bn + warp_n + nt * 8 + tg * 2;
            const float b0 = bias[col], b1 = bias[col + 1];
#pragma unroll
            for (int h = 0; h < 2; h++) {
                const int row = bm + warp_m + mt * 16 + g + h * 8;
                float v0 = acc[mt][nt][h * 2 + 0] + b0;
                float v1 = acc[mt][nt][h * 2 + 1] + b1;
                if (flags & 2) {
                    v0 = 0.5f * v0 * (1.0f + erff(v0 * 0.70710678118654752f));
                    v1 = 0.5f * v1 * (1.0f + erff(v1 * 0.70710678118654752f));
                }
                float* cp = C + (size_t)row * N + col;
                if (flags & 1) { v0 += cp[0]; v1 += cp[1]; }
                *(float2*)cp = make_float2(v0, v1);
            }
        }
    }
}

// ---------------------------------------------------------------------------
// Elementwise / small kernels
// ---------------------------------------------------------------------------
__global__ void copy4_k(float* __restrict__ dst, const float* __restrict__ src, size_t n4) {
    size_t i = (size_t)blockIdx.x * blockDim.x + threadIdx.x;
    size_t st = (size_t)gridDim.x * blockDim.x;
    for (; i < n4; i += st) ((float4*)dst)[i] = ((const float4*)src)[i];
}

__global__ void fill_k(float* __restrict__ dst, size_t n, float v) {
    size_t i = (size_t)blockIdx.x * blockDim.x + threadIdx.x;
    size_t st = (size_t)gridDim.x * blockDim.x;
    for (; i < n; i += st) dst[i] = v;
}

__global__ void axpyg_k(float* __restrict__ dst, const float* __restrict__ src,
                        const float* __restrict__ g, size_t n) {
    size_t i = (size_t)blockIdx.x * blockDim.x + threadIdx.x;
    size_t st = (size_t)gridDim.x * blockDim.x;
    for (; i < n; i += st) dst[i] = fmaf(g[i & (D_ - 1)], src[i], dst[i]);
}

__global__ void concat_k(float* __restrict__ comb, const float* __restrict__ q,
                         const float* __restrict__ ins) {
    size_t n = SM;
    size_t i = (size_t)blockIdx.x * blockDim.x + threadIdx.x;
    size_t st = (size_t)gridDim.x * blockDim.x;
    for (; i < n; i += st) {
        int b = (int)(i / (128 * D_));
        int rem = (int)(i % (128 * D_));
        int t = rem / D_, d = rem % D_;
        comb[i] = (t < QN) ? q[((size_t)b * QN + t) * D_ + d]
                           : ins[((size_t)b * IN_ + (t - QN)) * D_ + d];
    }
}

__global__ void slice_k(float* __restrict__ qry, const float* __restrict__ comb) {
    size_t n = (size_t)B_ * QN * D_;
    size_t i = (size_t)blockIdx.x * blockDim.x + threadIdx.x;
    size_t st = (size_t)gridDim.x * blockDim.x;
    for (; i < n; i += st) {
        int b = (int)(i / (QN * D_));
        int rem = (int)(i % (QN * D_));
        qry[i] = comb[(size_t)b * 128 * D_ + rem];
    }
}

// d_out is FLOAT32; reference is bf16-quantized -> emit bf16-rounded fp32.
__global__ void out_f32_k(float* __restrict__ out, const float* __restrict__ x, size_t n) {
    size_t i = (size_t)blockIdx.x * blockDim.x + threadIdx.x;
    size_t st = (size_t)gridDim.x * blockDim.x;
    for (; i < n; i += st) out[i] = __bfloat162float(__float2bfloat16(x[i]));
}

__global__ void add_pos_k(float* __restrict__ ctx, const int* __restrict__ coords,
                          const float* __restrict__ pe) {
    const int bl = blockIdx.x, tid = threadIdx.x;
    const int c0 = coords[bl * 2]     / 256;
    const int c1 = coords[bl * 2 + 1] / 256;
    const size_t pidx = (size_t)(c0 * 256 + c1) * D_;
    float4* dst = (float4*)(ctx + (size_t)bl * D_);
    const float4* src = (const float4*)(pe + pidx);
    float4 a = dst[tid], b = src[tid];
    a.x += b.x; a.y += b.y; a.z += b.z; a.w += b.w;
    dst[tid] = a;
}

// ---------------------------------------------------------------------------
// LayerNorm
// ---------------------------------------------------------------------------
__global__ __launch_bounds__(128) void layernorm_k(
    const float* __restrict__ x, float* __restrict__ y,
    const float* __restrict__ g, const float* __restrict__ bet) {
    const int row = blockIdx.x, tid = threadIdx.x;
    const float4 v = ((const float4*)(x + (size_t)row * D_))[tid];
    float s = v.x + v.y + v.z + v.w;
    float sq = v.x * v.x + v.y * v.y + v.z * v.z + v.w * v.w;
#pragma unroll
    for (int o = 16; o > 0; o >>= 1) {
        s  += __shfl_xor_sync(0xffffffffu, s, o);
        sq += __shfl_xor_sync(0xffffffffu, sq, o);
    }
    __shared__ float sh[8];
    if ((tid & 31) == 0) { sh[tid >> 5] = s; sh[4 + (tid >> 5)] = sq; }
    __syncthreads();
    s  = sh[0] + sh[1] + sh[2] + sh[3];
    sq = sh[4] + sh[5] + sh[6] + sh[7];
    const float mean = s * (1.0f / D_);
    const float var  = sq * (1.0f / D_) - mean * mean;
    const float rs = rsqrtf(var + 1e-5f);
    const float4 gv = ((const float4*)g)[tid];
    const float4 bv = ((const float4*)bet)[tid];
    float4 o;
    o.x = (v.x - mean) * rs * gv.x + bv.x;
    o.y = (v.y - mean) * rs * gv.y + bv.y;
    o.z = (v.z - mean) * rs * gv.z + bv.z;
    o.w = (v.w - mean) * rs * gv.w + bv.w;
    ((float4*)(y + (size_t)row * D_))[tid] = o;
}

// ---------------------------------------------------------------------------
// SGEMM (NT) fallback for small M
// ---------------------------------------------------------------------------
__global__ __launch_bounds__(256) void gemm_nt(
    const float* __restrict__ A, const float* __restrict__ W,
    const float* __restrict__ bias, float* __restrict__ C,
    int M, int N, int K, int flags) {
    __shared__ float As[16 * 136];
    __shared__ float Bs[16 * 136];
    const int tid = threadIdx.x;
    const int bm = blockIdx.y * 128, bn = blockIdx.x * 128;
    const int tr = (tid & 15) * 8;
    const int tc = (tid >> 4) * 8;
    const int lr0 = tid >> 1;
    const int lk0 = (tid & 1) * 8;
    float acc[8][8];
#pragma unroll
    for (int x = 0; x < 8; x++)
#pragma unroll
        for (int y = 0; y < 8; y++) acc[x][y] = 0.f;

    for (int k0 = 0; k0 < K; k0 += 16) {
        {
            const int r = bm + lr0;
            float4 a0, a1;
            if (r < M) {
                const float* src = A + (size_t)r * K + k0 + lk0;
                a0 = *(const float4*)src; a1 = *(const float4*)(src + 4);
            } else {
                a0 = make_float4(0, 0, 0, 0); a1 = a0;
            }
            As[(lk0 + 0) * 136 + lr0] = a0.x; As[(lk0 + 1) * 136 + lr0] = a0.y;
            As[(lk0 + 2) * 136 + lr0] = a0.z; As[(lk0 + 3) * 136 + lr0] = a0.w;
            As[(lk0 + 4) * 136 + lr0] = a1.x; As[(lk0 + 5) * 136 + lr0] = a1.y;
            As[(lk0 + 6) * 136 + lr0] = a1.z; As[(lk0 + 7) * 136 + lr0] = a1.w;
            const float* srcb = W + (size_t)(bn + lr0) * K + k0 + lk0;
            float4 b0 = *(const float4*)srcb; float4 b1 = *(const float4*)(srcb + 4);
            Bs[(lk0 + 0) * 136 + lr0] = b0.x; Bs[(lk0 + 1) * 136 + lr0] = b0.y;
            Bs[(lk0 + 2) * 136 + lr0] = b0.z; Bs[(lk0 + 3) * 136 + lr0] = b0.w;
            Bs[(lk0 + 4) * 136 + lr0] = b1.x; Bs[(lk0 + 5) * 136 + lr0] = b1.y;
            Bs[(lk0 + 6) * 136 + lr0] = b1.z; Bs[(lk0 + 7) * 136 + lr0] = b1.w;
        }
        __syncthreads();
#pragma unroll
        for (int kk = 0; kk < 16; kk++) {
            const float* ar = As + kk * 136 + tr;
            const float* br = Bs + kk * 136 + tc;
            float4 a0 = *(const float4*)ar, a1 = *(const float4*)(ar + 4);
            float4 b0 = *(const float4*)br, b1 = *(const float4*)(br + 4);
            float ra[8] = {a0.x, a0.y, a0.z, a0.w, a1.x, a1.y, a1.z, a1.w};
            float rb[8] = {b0.x, b0.y, b0.z, b0.w, b1.x, b1.y, b1.z, b1.w};
#pragma unroll
            for (int x = 0; x < 8; x++)
#pragma unroll
                for (int y = 0; y < 8; y++)
                    acc[x][y] = fmaf(ra[x], rb[y], acc[x][y]);
        }
        __syncthreads();
    }
#pragma unroll
    for (int x = 0; x < 8; x++) {
        const int r = bm + tr + x;
        if (r >= M) break;
        float* crow = C + (size_t)r * N + bn + tc;
#pragma unroll
        for (int y = 0; y < 8; y++) {
            float c = acc[x][y] + bias[bn + tc + y];
            if (flags & 2) c = 0.5f * c * (1.0f + erff(c * 0.70710678118654752f));
            if (flags & 1) c += crow[y];
            crow[y] = c;
        }
    }
}

// ---------------------------------------------------------------------------
// Flash dilated-attention branch
// ---------------------------------------------------------------------------
__global__ __launch_bounds__(128) void dil_branch_k(
    const float* __restrict__ Qm, const float* __restrict__ Km, const float* __restrict__ Vm,
    float* __restrict__ ofb, float* __restrict__ lfb, int w, int r) {
    __shared__ float Ks[32 * 64];
    __shared__ float Vs[32 * 64];
    __shared__ float Ss[32 * 128];
    const int nseg = L_ / w;
    int t = blockIdx.x;
    const int qt = t & 3; t >>= 2;
    const int h = t & 7; t >>= 3;
    const int seg = t % nseg; const int b = t / nseg;
    const int base = seg * w + (h & (r - 1));
    const int tid = threadIdx.x;
    const int j = qt * 128 + tid;
    const size_t rowq = (size_t)b * L_ + base + (size_t)r * j;
    const float* qp = Qm + rowq * D_ + h * DH_;
    float q[64];
#pragma unroll
    for (int d = 0; d < 64; d += 4) {
        float4 tv = *(const float4*)(qp + d);
        q[d] = tv.x; q[d + 1] = tv.y; q[d + 2] = tv.z; q[d + 3] = tv.w;
    }
    float o[64];
#pragma unroll
    for (int d = 0; d < 64; d++) o[d] = 0.f;
    float mv = -INFINITY, ls = 0.f;

    for (int kt = 0; kt < 16; kt++) {
        __syncthreads();
        for (int li = tid; li < 512; li += 128) {
            const int kk = li >> 4, dq = (li & 15) << 2;
            const size_t gp = ((size_t)b * L_ + base + (size_t)r * (kt * 32 + kk)) * D_
                              + h * DH_ + dq;
            *(float4*)(Ks + kk * 64 + dq) = *(const float4*)(Km + gp);
            *(float4*)(Vs + kk * 64 + dq) = *(const float4*)(Vm + gp);
        }
        __syncthreads();
        float tmax = -INFINITY;
#pragma unroll 1
        for (int kk = 0; kk < 32; kk++) {
            const float* kr = Ks + kk * 64;
            float s = 0.f;
#pragma unroll
            for (int d = 0; d < 64; d += 4) {
                float4 kv = *(const float4*)(kr + d);
                s = fmaf(q[d], kv.x, s);     s = fmaf(q[d + 1], kv.y, s);
                s = fmaf(q[d + 2], kv.z, s); s = fmaf(q[d + 3], kv.w, s);
            }
            s *= SCALE_;
            Ss[kk * 128 + tid] = s;
            tmax = fmaxf(tmax, s);
        }
        const float mn = fmaxf(mv, tmax);
        const float corr = __expf(mv - mn);
        ls *= corr;
#pragma unroll
        for (int d = 0; d < 64; d++) o[d] *= corr;
#pragma unroll 1
        for (int kk = 0; kk < 32; kk++) {
            const float p = __expf(Ss[kk * 128 + tid] - mn);
            ls += p;
            const float* vr = Vs + kk * 64;
#pragma unroll
            for (int d = 0; d < 64; d += 4) {
                float4 vv = *(const float4*)(vr + d);
                o[d]     = fmaf(p, vv.x, o[d]);
                o[d + 1] = fmaf(p, vv.y, o[d + 1]);
                o[d + 2] = fmaf(p, vv.z, o[d + 2]);
                o[d + 3] = fmaf(p, vv.w, o[d + 3]);
            }
        }
        mv = mn;
    }
    const float inv = 1.0f / ls;
    float* op = ofb + rowq * D_ + h * DH_;
#pragma unroll
    for (int d = 0; d < 64; d += 4) {
        float4 tv = make_float4(o[d] * inv, o[d + 1] * inv, o[d + 2] * inv, o[d + 3] * inv);
        *(float4*)(op + d) = tv;
    }
    lfb[rowq * H_ + h] = mv + logf(ls);
}

// ---------------------------------------------------------------------------
// Flash generic attention partial (split-KV)
// ---------------------------------------------------------------------------
__global__ __launch_bounds__(128) void attn_part_k(
    const float* __restrict__ Qm, const float* __restrict__ Km, const float* __restrict__ Vm,
    float* __restrict__ op_, float* __restrict__ lse_,
    int Tq, int Tk, int chunk) {
    __shared__ float Ks[32 * 64];
    __shared__ float Vs[32 * 64];
    __shared__ float Ss[32 * 128];
    const int split = blockIdx.x;
    const int b = blockIdx.y >> 3;
    const int h = blockIdx.y & 7;
    const int qt = blockIdx.z;
    const int tid = threadIdx.x;
    const int qi = qt * 128 + tid;
    const bool act = qi < Tq;
    const float* qp = Qm + ((size_t)b * Tq + (act ? qi : 0)) * D_ + h * DH_;
    float q[64];
#pragma unroll
    for (int d = 0; d < 64; d += 4) {
        float4 tv = *(const float4*)(qp + d);
        q[d] = tv.x; q[d + 1] = tv.y; q[d + 2] = tv.z; q[d + 3] = tv.w;
    }
    float o[64];
#pragma unroll
    for (int d = 0; d < 64; d++) o[d] = 0.f;
    float mv = -INFINITY, ls = 0.f;
    const int k0 = split * chunk;
    const int ntile = chunk / 32;

    for (int kt = 0; kt < ntile; kt++) {
        __syncthreads();
        for (int li = tid; li < 512; li += 128) {
            const int kk = li >> 4, dq = (li & 15) << 2;
            const size_t gp = ((size_t)b * Tk + k0 + kt * 32 + kk) * D_ + h * DH_ + dq;
            *(float4*)(Ks + kk * 64 + dq) = *(const float4*)(Km + gp);
            *(float4*)(Vs + kk * 64 + dq) = *(const float4*)(Vm + gp);
        }
        __syncthreads();
        float tmax = -INFINITY;
#pragma unroll 1
        for (int kk = 0; kk < 32; kk++) {
            const float* kr = Ks + kk * 64;
            float s = 0.f;
#pragma unroll
            for (int d = 0; d < 64; d += 4) {
                float4 kv = *(const float4*)(kr + d);
                s = fmaf(q[d], kv.x, s);     s = fmaf(q[d + 1], kv.y, s);
                s = fmaf(q[d + 2], kv.z, s); s = fmaf(q[d + 3], kv.w, s);
            }
            s *= SCALE_;
            Ss[kk * 128 + tid] = s;
            tmax = fmaxf(tmax, s);
        }
        const float mn = fmaxf(mv, tmax);
        const float corr = __expf(mv - mn);
        ls *= corr;
#pragma unroll
        for (int d = 0; d < 64; d++) o[d] *= corr;
#pragma unroll 1
        for (int kk = 0; kk < 32; kk++) {
            const float p = __expf(Ss[kk * 128 + tid] - mn);
            ls += p;
            const float* vr = Vs + kk * 64;
#pragma unroll
            for (int d = 0; d < 64; d += 4) {
                float4 vv = *(const float4*)(vr + d);
                o[d]     = fmaf(p, vv.x, o[d]);
                o[d + 1] = fmaf(p, vv.y, o[d + 1]);
                o[d + 2] = fmaf(p, vv.z, o[d + 2]);
                o[d + 3] = fmaf(p, vv.w, o[d + 3]);
            }
        }
        mv = mn;
    }
    if (act) {
        const size_t RH = (size_t)B_ * Tq * H_;
        const size_t idx = (size_t)split * RH + ((size_t)b * Tq + qi) * H_ + h;
        const float inv = 1.0f / ls;
        float* op = op_ + idx * 64;
#pragma unroll
        for (int d = 0; d < 64; d += 4) {
            float4 tv = make_float4(o[d] * inv, o[d + 1] * inv, o[d + 2] * inv, o[d + 3] * inv);
            *(float4*)(op + d) = tv;
        }
        lse_[idx] = mv + logf(ls);
    }
}

// ---------------------------------------------------------------------------
// LSE-weighted combine
// ---------------------------------------------------------------------------
__global__ __launch_bounds__(64) void combine_k(
    const float* __restrict__ op, const float* __restrict__ lse,
    float* __restrict__ out, int ns, size_t RH) {
    const size_t i = blockIdx.x;
    const int tid = threadIdx.x;
    float m = -INFINITY;
    for (int s = 0; s < ns; s++) {
        const float l = lse[(size_t)s * RH + i];
        if (l > -1e8f) m = fmaxf(m, l);
    }
    float tot = 0.f, acc = 0.f;
    for (int s = 0; s < ns; s++) {
        const float l = lse[(size_t)s * RH + i];
        if (l > -1e8f) {
            const float w = __expf(l - m);
            tot += w;
            acc = fmaf(w, op[((size_t)s * RH + i) * 64 + tid], acc);
        }
    }
    out[i * 64 + tid] = acc / tot;
}

// ---------------------------------------------------------------------------
// Host orchestration
// ---------------------------------------------------------------------------
struct SplitBufs {
    __nv_bfloat16 *ahi, *alo, *whi, *wlo;
};

static inline void gemm_big(const SplitBufs& sb, const float* A, const float* W,
                            const float* bias, float* C,
                            int M, int N, int K, int flags, bool convA) {
    if (convA) split_k<<<2048, 256>>>(A, sb.ahi, sb.alo, (size_t)M * K / 4);
    split_k<<<512, 256>>>(W, sb.whi, sb.wlo, (size_t)N * K / 4);
    dim3 g(N / 128, M / 128);
    gemm_mma2<<<g, 256, GM2_SMEM>>>(sb.ahi, sb.alo, sb.whi, sb.wlo, bias, C, M, N, K, flags);
}

static inline void gemm_small(const float* A, const float* W, const float* bias, float* C,
                              int M, int N, int K, int flags) {
    dim3 g(N / 128, (M + 127) / 128);
    gemm_nt<<<g, 256>>>(A, W, bias, C, M, N, K, flags);
}

extern "C" void kernel_launch(void* const* d_in, const int* in_sizes, int n_in,
                              void* d_out, int out_size) {
    (void)in_sizes; (void)n_in; (void)out_size;
    cudaFuncSetAttribute(gemm_mma2, cudaFuncAttributeMaxDynamicSharedMemorySize, GM2_SMEM);

    const float* querys   = (const float*)d_in[0];
    const float* contexts = (const float*)d_in[1];
    const float* instr    = (const float*)d_in[2];
    const int*   coords   = (const int*)d_in[3];
    const float* pe       = (const float*)d_in[4];
    const float* qkv_w    = (const float*)d_in[5];
    const float* qkv_b    = (const float*)d_in[6];
    const float* ln_ln    = (const float*)d_in[7];
    const float* fc1_w    = (const float*)d_in[8];
    const float* fc1_b    = (const float*)d_in[9];
    const float* fc2_w    = (const float*)d_in[10];
    const float* fc2_b    = (const float*)d_in[11];
    const float* ln_fin   = (const float*)d_in[12];
    const float* sa_w     = (const float*)d_in[13];
    const float* sa_b     = (const float*)d_in[14];
    const float* sa_ln    = (const float*)d_in[15];
    const float* sa_g     = (const float*)d_in[16];
    const float* sa_f1w   = (const float*)d_in[17];
    const float* sa_f1b   = (const float*)d_in[18];
    const float* sa_f2w   = (const float*)d_in[19];
    const float* sa_f2b   = (const float*)d_in[20];
    const float* ca_w     = (const float*)d_in[21];
    const float* ca_b     = (const float*)d_in[22];
    const float* ca_ln    = (const float*)d_in[23];

    float* g;
    { void* p = nullptr; cudaGetSymbolAddress(&p, gbuf); g = (float*)p; }
    SplitBufs sb;
    { void* p = nullptr; cudaGetSymbolAddress(&p, g_ahi); sb.ahi = (__nv_bfloat16*)p; }
    { void* p = nullptr; cudaGetSymbolAddress(&p, g_alo); sb.alo = (__nv_bfloat16*)p; }
    { void* p = nullptr; cudaGetSymbolAddress(&p, g_whi); sb.whi = (__nv_bfloat16*)p; }
    { void* p = nullptr; cudaGetSymbolAddress(&p, g_wlo); sb.wlo = (__nv_bfloat16*)p; }

    float *X = g + OFF_X, *Hb = g + OFF_H, *Qb = g + OFF_Q, *Kb = g + OFF_K,
          *Vb = g + OFF_V, *OC = g + OFF_OC, *CTX = g + OFF_CTX, *O5 = g + OFF_O5,
          *FFb = g + OFF_FF, *LSE5 = g + OFF_LSE5, *COMB = g + OFF_COMB,
          *HS = g + OFF_HS, *OS = g + OFF_OS, *Tt = g + OFF_T, *FFS = g + OFF_FFS,
          *QRY = g + OFF_QRY, *PART = g + OFF_PART, *PLSE = g + OFF_PLSE;

    copy4_k<<<4096, 256>>>(CTX, contexts, S_ / 4);
    add_pos_k<<<B_ * L_, 128>>>(CTX, coords, pe);
    copy4_k<<<64, 256>>>(QRY, querys, (size_t)B_ * QN * D_ / 4);

    const int WS[5] = {512, 1024, 2048, 4096, 8192};
    const int RS[5] = {1, 2, 4, 8, 16};
    const int ML = B_ * L_;

    for (int i = 0; i < 2; i++) {
        copy4_k<<<4096, 256>>>(X, CTX, S_ / 4);
        for (int j = 0; j < 2; j++) {
            const int ij = i * 2 + j;
            const float* lg0 = ln_ln + (size_t)((ij * 2 + 0) * 2) * D_;
            layernorm_k<<<ML, 128>>>(X, Hb, lg0, lg0 + D_);
            const float* Wq = qkv_w + (size_t)(ij * 4) * DD;
            const float* bq = qkv_b + (size_t)(ij * 4) * D_;
            gemm_big(sb, Hb, Wq,          bq,          Qb, ML, D_, D_, 0, true);
            gemm_big(sb, Hb, Wq + DD,     bq + D_,     Kb, ML, D_, D_, 0, false);
            gemm_big(sb, Hb, Wq + 2 * DD, bq + 2 * D_, Vb, ML, D_, D_, 0, false);
            fill_k<<<2560, 256>>>(LSE5, 5 * BLH, NEGV);
            for (int br = 0; br < 5; br++) {
                const int w = WS[br], r = RS[br], nseg = L_ / w;
                dil_branch_k<<<B_ * nseg * H_ * 4, 128>>>(
                    Qb, Kb, Vb, O5 + (size_t)br * S_, LSE5 + (size_t)br * BLH, w, r);
            }
            combine_k<<<(unsigned)BLH, 64>>>(O5, LSE5, OC, 5, BLH);
            gemm_big(sb, OC, Wq + 3 * DD, bq + 3 * D_, X, ML, D_, D_, 1, true);
            const float* lg1 = ln_ln + (size_t)((ij * 2 + 1) * 2) * D_;
            layernorm_k<<<ML, 128>>>(X, Hb, lg1, lg1 + D_);
            gemm_big(sb, Hb, fc1_w + (size_t)ij * FF_ * D_, fc1_b + (size_t)ij * FF_,
                     FFb, ML, FF_, D_, 2, true);
            gemm_big(sb, FFb, fc2_w + (size_t)ij * D_ * FF_, fc2_b + (size_t)ij * D_,
                     X, ML, D_, FF_, 1, true);
        }
        layernorm_k<<<ML, 128>>>(X, CTX, ln_fin + (size_t)i * 2 * D_,
                                 ln_fin + (size_t)i * 2 * D_ + D_);
        concat_k<<<512, 256>>>(COMB, QRY, instr);
        const float* sl0 = sa_ln + (size_t)((i * 2 + 0) * 2) * D_;
        layernorm_k<<<B_ * 128, 128>>>(COMB, HS, sl0, sl0 + D_);
        const float* Ws = sa_w + (size_t)i * 4 * DD;
        const float* bs = sa_b + (size_t)i * 4 * D_;
        gemm_small(HS, Ws,          bs,          Qb, B_ * 128, D_, D_, 0);
        gemm_small(HS, Ws + DD,     bs + D_,     Kb, B_ * 128, D_, D_, 0);
        gemm_small(HS, Ws + 2 * DD, bs + 2 * D_, Vb, B_ * 128, D_, D_, 0);
        attn_part_k<<<dim3(1, B_ * H_, 1), 128>>>(Qb, Kb, Vb, PART, PLSE, 128, 128, 128);
        combine_k<<<B_ * 128 * H_, 64>>>(PART, PLSE, OS, 1, (size_t)B_ * 128 * H_);
        gemm_small(OS, Ws + 3 * DD, bs + 3 * D_, Tt, B_ * 128, D_, D_, 0);
        axpyg_k<<<128, 256>>>(COMB, Tt, sa_g + (size_t)(i * 2 + 0) * D_, SM);
        const float* sl1 = sa_ln + (size_t)((i * 2 + 1) * 2) * D_;
        layernorm_k<<<B_ * 128, 128>>>(COMB, HS, sl1, sl1 + D_);
        gemm_small(HS, sa_f1w + (size_t)i * FF_ * D_, sa_f1b + (size_t)i * FF_,
                   FFS, B_ * 128, FF_, D_, 2);
        gemm_small(FFS, sa_f2w + (size_t)i * D_ * FF_, sa_f2b + (size_t)i * D_,
                   Tt, B_ * 128, D_, FF_, 0);
        axpyg_k<<<128, 256>>>(COMB, Tt, sa_g + (size_t)(i * 2 + 1) * D_, SM);
        slice_k<<<32, 256>>>(QRY, COMB);
        const float* Wc = ca_w + (size_t)i * 4 * DD;
        const float* bc = ca_b + (size_t)i * 4 * D_;
        gemm_small(QRY, Wc, bc, Qb, B_ * QN, D_, D_, 0);
        gemm_big(sb, CTX, Wc + DD,     bc + D_,     Kb, ML, D_, D_, 0, true);
        gemm_big(sb, CTX, Wc + 2 * DD, bc + 2 * D_, Vb, ML, D_, D_, 0, false);
        attn_part_k<<<dim3(32, B_ * H_, 1), 128>>>(Qb, Kb, Vb, PART, PLSE, QN, L_, 256);
        combine_k<<<B_ * QN * H_, 64>>>(PART, PLSE, OS, 32, (size_t)B_ * QN * H_);
        gemm_small(OS, Wc + 3 * DD, bc + 3 * D_, QRY, B_ * QN, D_, D_, 1);
        layernorm_k<<<B_ * QN, 128>>>(QRY, QRY, ca_ln + (size_t)i * 2 * D_,
                                      ca_ln + (size_t)i * 2 * D_ + D_);
    }
    out_f32_k<<<32, 256>>>((float*)d_out, QRY, (size_t)B_ * QN * D_);
}

// round 17
// speedup vs baseline: 1.8562x; 1.2303x over previous
#include <cuda_runtime.h>
#include <cuda_bf16.h>
#include <math.h>
#include <stdint.h>

// ---------------------------------------------------------------------------
// Problem constants
// ---------------------------------------------------------------------------
#define B_   2
#define L_   8192
#define QN   32
#define IN_  96
#define D_   512
#define H_   8
#define DH_  64
#define FF_  2048
#define SCALE_ 0.125f
#define NEGV  (-1.0e9f)

constexpr size_t S_  = (size_t)B_ * L_ * D_;
constexpr size_t BLH = (size_t)B_ * L_ * H_;
constexpr size_t SM  = (size_t)B_ * 128 * D_;
constexpr size_t DD  = (size_t)D_ * D_;

constexpr size_t OFF_X    = 0;
constexpr size_t OFF_H    = S_;
constexpr size_t OFF_Q    = 2 * S_;
constexpr size_t OFF_K    = 3 * S_;
constexpr size_t OFF_V    = 4 * S_;
constexpr size_t OFF_OC   = 5 * S_;
constexpr size_t OFF_CTX  = 6 * S_;
constexpr size_t OFF_O5   = 7 * S_;
constexpr size_t OFF_FF   = 12 * S_;
constexpr size_t OFF_LSE5 = 16 * S_;
constexpr size_t OFF_COMB = OFF_LSE5 + 5 * BLH;
constexpr size_t OFF_HS   = OFF_COMB + SM;
constexpr size_t OFF_OS   = OFF_HS + SM;
constexpr size_t OFF_T    = OFF_OS + SM;
constexpr size_t OFF_FFS  = OFF_T + SM;
constexpr size_t OFF_QRY  = OFF_FFS + (size_t)B_ * 128 * FF_;
constexpr size_t OFF_PART = OFF_QRY + (size_t)B_ * QN * D_;
constexpr size_t OFF_PLSE = OFF_PART + (size_t)32 * B_ * QN * H_ * DH_;
constexpr size_t TOTAL_F  = OFF_PLSE + (size_t)32 * B_ * QN * H_;

__device__ float gbuf[TOTAL_F];

// bf16 scratch (hi planes only): A for largest activation (16384 x 2048),
// W for largest weight (2048 x 512).
constexpr size_t AMAX = (size_t)16384 * 2048;
constexpr size_t WMAX = (size_t)2048 * 512;
__device__ __nv_bfloat16 g_ahi[AMAX];
__device__ __nv_bfloat16 g_whi[WMAX];

// ---------------------------------------------------------------------------
// PTX helpers (baseline PTX only; no arch-'a' features)
// ---------------------------------------------------------------------------
__device__ __forceinline__ uint32_t smem_u32(const void* p) {
    uint32_t a;
    asm("{ .reg .u64 t; cvta.to.shared.u64 t, %1; cvt.u32.u64 %0, t; }" : "=r"(a) : "l"(p));
    return a;
}
__device__ __forceinline__ void ldsm_x4(uint32_t& r0, uint32_t& r1, uint32_t& r2,
                                        uint32_t& r3, uint32_t addr) {
    asm volatile("ldmatrix.sync.aligned.m8n8.x4.shared.b16 {%0,%1,%2,%3}, [%4];"
                 : "=r"(r0), "=r"(r1), "=r"(r2), "=r"(r3) : "r"(addr));
}
__device__ __forceinline__ void mma_bf16(float* d, const uint32_t* a, uint32_t b0, uint32_t b1) {
    asm volatile(
        "mma.sync.aligned.m16n8k16.row.col.f32.bf16.bf16.f32 "
        "{%0,%1,%2,%3}, {%4,%5,%6,%7}, {%8,%9}, {%0,%1,%2,%3};"
        : "+f"(d[0]), "+f"(d[1]), "+f"(d[2]), "+f"(d[3])
        : "r"(a[0]), "r"(a[1]), "r"(a[2]), "r"(a[3]), "r"(b0), "r"(b1));
}
#define CP_ASYNC16(dst, src) \
    asm volatile("cp.async.cg.shared.global [%0], [%1], 16;" :: "r"(dst), "l"(src))
#define CP_COMMIT() asm volatile("cp.async.commit_group;" ::: "memory")

// ---------------------------------------------------------------------------
// fp32 -> bf16 convert (hi plane only), vectorized by 4. n4 = n/4.
// ---------------------------------------------------------------------------
__global__ void split1_k(const float* __restrict__ x, __nv_bfloat16* __restrict__ hi,
                         size_t n4) {
    size_t i = (size_t)blockIdx.x * blockDim.x + threadIdx.x;
    size_t st = (size_t)gridDim.x * blockDim.x;
    for (; i < n4; i += st) {
        const float4 v = ((const float4*)x)[i];
        __nv_bfloat162 p0(__float2bfloat16(v.x), __float2bfloat16(v.y));
        __nv_bfloat162 p1(__float2bfloat16(v.z), __float2bfloat16(v.w));
        uint2 u;
        u.x = *(uint32_t*)&p0; u.y = *(uint32_t*)&p1;
        ((uint2*)hi)[i] = u;
    }
}

// ---------------------------------------------------------------------------
// Single-plane bf16 tensor-core GEMM, cp.async double-buffered.
// C[M,N] = A @ W^T + bias; flags 1=accum, 2=gelu. M,N mult 128, K mult 32.
// smem: 2 stages x (A tile + W tile), tile = 128 rows x 40 bf16 (80B) = 10240B
// -> 40960 B dynamic.
// ---------------------------------------------------------------------------
#define GM1_SMEM 40960

__device__ __forceinline__ void stage_load(
    uint32_t sbase, int stage, int ch,
    const __nv_bfloat16* Ahi, const __nv_bfloat16* Whi,
    int bm, int bn, int K, int sr, int ss) {
    const int kb = ch << 5;
    const uint32_t d0 = sbase + stage * 20480 + (uint32_t)(sr * 80 + ss * 16);
    const size_t ao = (size_t)(bm + sr) * K + kb + ss * 8;
    const size_t bo = (size_t)(bn + sr) * K + kb + ss * 8;
    CP_ASYNC16(d0,         Ahi + ao); CP_ASYNC16(d0 + 16,         Ahi + ao + 8);
    CP_ASYNC16(d0 + 10240, Whi + bo); CP_ASYNC16(d0 + 10240 + 16, Whi + bo + 8);
}

__global__ __launch_bounds__(256) void gemm_mma1(
    const __nv_bfloat16* __restrict__ Ahi, const __nv_bfloat16* __restrict__ Whi,
    const float* __restrict__ bias, float* __restrict__ C,
    int M, int N, int K, int flags) {
    extern __shared__ char dsm[];
    const uint32_t sbase = smem_u32(dsm);
    const int tid = threadIdx.x;
    const int wid = tid >> 5, lane = tid & 31;
    const int bm = blockIdx.y * 128, bn = blockIdx.x * 128;
    const int warp_m = (wid & 3) * 32, warp_n = (wid >> 2) * 64;

    const int mi = lane >> 3, l7 = lane & 7;
    const int a_r8 = (mi & 1) * 8 + l7, a_k8 = (mi >> 1) * 8;
    const int b_r8 = (mi >> 1) * 8 + l7, b_k8 = (mi & 1) * 8;

    const int sr = tid >> 1, ss = (tid & 1) * 2;

    float acc[2][8][4];
#pragma unroll
    for (int mt = 0; mt < 2; mt++)
#pragma unroll
        for (int nt = 0; nt < 8; nt++)
#pragma unroll
            for (int c = 0; c < 4; c++) acc[mt][nt][c] = 0.f;

    const int nch = K >> 5;
    stage_load(sbase, 0, 0, Ahi, Whi, bm, bn, K, sr, ss);
    CP_COMMIT();

    for (int ch = 0; ch < nch; ch++) {
        const int cur = ch & 1;
        const bool more = (ch + 1) < nch;
        if (more) {
            stage_load(sbase, cur ^ 1, ch + 1, Ahi, Whi, bm, bn, K, sr, ss);
            CP_COMMIT();
            asm volatile("cp.async.wait_group 1;" ::: "memory");
        } else {
            asm volatile("cp.async.wait_group 0;" ::: "memory");
        }
        __syncthreads();
        const uint32_t tb = sbase + (uint32_t)(cur * 20480);
#pragma unroll
        for (int ks = 0; ks < 2; ks++) {
            const int k0 = ks * 16;
            uint32_t a[2][4];
#pragma unroll
            for (int mt = 0; mt < 2; mt++) {
                const uint32_t off =
                    (uint32_t)(((warp_m + mt * 16 + a_r8) * 40 + k0 + a_k8) * 2);
                ldsm_x4(a[mt][0], a[mt][1], a[mt][2], a[mt][3], tb + off);
            }
#pragma unroll
            for (int np = 0; np < 4; np++) {
                const uint32_t off =
                    (uint32_t)(((warp_n + np * 16 + b_r8) * 40 + k0 + b_k8) * 2);
                uint32_t b0, b1, b2, b3;
                ldsm_x4(b0, b1, b2, b3, tb + 10240 + off);
#pragma unroll
                for (int mt = 0; mt < 2; mt++) {
                    mma_bf16(acc[mt][np * 2 + 0], a[mt], b0, b1);
                    mma_bf16(acc[mt][np * 2 + 1], a[mt], b2, b3);
                }
            }
        }
        __syncthreads();
    }

    const int g = lane >> 2, tg = lane & 3;
#pragma unroll
    for (int mt = 0; mt < 2; mt++) {
#pragma unroll
        for (int nt = 0; nt < 8; nt++) {
            const int col = bn + warp_n + nt * 8 + tg * 2;
            const float b0 = bias[col], b1 = bias[col + 1];
#pragma unroll
            for (int h = 0; h < 2; h++) {
                const int row = bm + warp_m + mt * 16 + g + h * 8;
                float v0 = acc[mt][nt][h * 2 + 0] + b0;
                float v1 = acc[mt][nt][h * 2 + 1] + b1;
                if (flags & 2) {
                    v0 = 0.5f * v0 * (1.0f + erff(v0 * 0.70710678118654752f));
                    v1 = 0.5f * v1 * (1.0f + erff(v1 * 0.70710678118654752f));
                }
                float* cp = C + (size_t)row * N + col;
                if (flags & 1) { v0 += cp[0]; v1 += cp[1]; }
                *(float2*)cp = make_float2(v0, v1);
            }
        }
    }
}

// ---------------------------------------------------------------------------
// Elementwise / small kernels
// ---------------------------------------------------------------------------
__global__ void copy4_k(float* __restrict__ dst, const float* __restrict__ src, size_t n4) {
    size_t i = (size_t)blockIdx.x * blockDim.x + threadIdx.x;
    size_t st = (size_t)gridDim.x * blockDim.x;
    for (; i < n4; i += st) ((float4*)dst)[i] = ((const float4*)src)[i];
}

__global__ void fill_k(float* __restrict__ dst, size_t n, float v) {
    size_t i = (size_t)blockIdx.x * blockDim.x + threadIdx.x;
    size_t st = (size_t)gridDim.x * blockDim.x;
    for (; i < n; i += st) dst[i] = v;
}

__global__ void axpyg_k(float* __restrict__ dst, const float* __restrict__ src,
                        const float* __restrict__ g, size_t n) {
    size_t i = (size_t)blockIdx.x * blockDim.x + threadIdx.x;
    size_t st = (size_t)gridDim.x * blockDim.x;
    for (; i < n; i += st) dst[i] = fmaf(g[i & (D_ - 1)], src[i], dst[i]);
}

__global__ void concat_k(float* __restrict__ comb, const float* __restrict__ q,
                         const float* __restrict__ ins) {
    size_t n = SM;
    size_t i = (size_t)blockIdx.x * blockDim.x + threadIdx.x;
    size_t st = (size_t)gridDim.x * blockDim.x;
    for (; i < n; i += st) {
        int b = (int)(i / (128 * D_));
        int rem = (int)(i % (128 * D_));
        int t = rem / D_, d = rem % D_;
        comb[i] = (t < QN) ? q[((size_t)b * QN + t) * D_ + d]
                           : ins[((size_t)b * IN_ + (t - QN)) * D_ + d];
    }
}

__global__ void slice_k(float* __restrict__ qry, const float* __restrict__ comb) {
    size_t n = (size_t)B_ * QN * D_;
    size_t i = (size_t)blockIdx.x * blockDim.x + threadIdx.x;
    size_t st = (size_t)gridDim.x * blockDim.x;
    for (; i < n; i += st) {
        int b = (int)(i / (QN * D_));
        int rem = (int)(i % (QN * D_));
        qry[i] = comb[(size_t)b * 128 * D_ + rem];
    }
}

// d_out is FLOAT32; reference is bf16-quantized -> emit bf16-rounded fp32.
__global__ void out_f32_k(float* __restrict__ out, const float* __restrict__ x, size_t n) {
    size_t i = (size_t)blockIdx.x * blockDim.x + threadIdx.x;
    size_t st = (size_t)gridDim.x * blockDim.x;
    for (; i < n; i += st) out[i] = __bfloat162float(__float2bfloat16(x[i]));
}

__global__ void add_pos_k(float* __restrict__ ctx, const int* __restrict__ coords,
                          const float* __restrict__ pe) {
    const int bl = blockIdx.x, tid = threadIdx.x;
    const int c0 = coords[bl * 2]     / 256;
    const int c1 = coords[bl * 2 + 1] / 256;
    const size_t pidx = (size_t)(c0 * 256 + c1) * D_;
    float4* dst = (float4*)(ctx + (size_t)bl * D_);
    const float4* src = (const float4*)(pe + pidx);
    float4 a = dst[tid], b = src[tid];
    a.x += b.x; a.y += b.y; a.z += b.z; a.w += b.w;
    dst[tid] = a;
}

// ---------------------------------------------------------------------------
// LayerNorm
// ---------------------------------------------------------------------------
__global__ __launch_bounds__(128) void layernorm_k(
    const float* __restrict__ x, float* __restrict__ y,
    const float* __restrict__ g, const float* __restrict__ bet) {
    const int row = blockIdx.x, tid = threadIdx.x;
    const float4 v = ((const float4*)(x + (size_t)row * D_))[tid];
    float s = v.x + v.y + v.z + v.w;
    float sq = v.x * v.x + v.y * v.y + v.z * v.z + v.w * v.w;
#pragma unroll
    for (int o = 16; o > 0; o >>= 1) {
        s  += __shfl_xor_sync(0xffffffffu, s, o);
        sq += __shfl_xor_sync(0xffffffffu, sq, o);
    }
    __shared__ float sh[8];
    if ((tid & 31) == 0) { sh[tid >> 5] = s; sh[4 + (tid >> 5)] = sq; }
    __syncthreads();
    s  = sh[0] + sh[1] + sh[2] + sh[3];
    sq = sh[4] + sh[5] + sh[6] + sh[7];
    const float mean = s * (1.0f / D_);
    const float var  = sq * (1.0f / D_) - mean * mean;
    const float rs = rsqrtf(var + 1e-5f);
    const float4 gv = ((const float4*)g)[tid];
    const float4 bv = ((const float4*)bet)[tid];
    float4 o;
    o.x = (v.x - mean) * rs * gv.x + bv.x;
    o.y = (v.y - mean) * rs * gv.y + bv.y;
    o.z = (v.z - mean) * rs * gv.z + bv.z;
    o.w = (v.w - mean) * rs * gv.w + bv.w;
    ((float4*)(y + (size_t)row * D_))[tid] = o;
}

// ---------------------------------------------------------------------------
// SGEMM (NT) fallback for small M (precision-critical querys path)
// ---------------------------------------------------------------------------
__global__ __launch_bounds__(256) void gemm_nt(
    const float* __restrict__ A, const float* __restrict__ W,
    const float* __restrict__ bias, float* __restrict__ C,
    int M, int N, int K, int flags) {
    __shared__ float As[16 * 136];
    __shared__ float Bs[16 * 136];
    const int tid = threadIdx.x;
    const int bm = blockIdx.y * 128, bn = blockIdx.x * 128;
    const int tr = (tid & 15) * 8;
    const int tc = (tid >> 4) * 8;
    const int lr0 = tid >> 1;
    const int lk0 = (tid & 1) * 8;
    float acc[8][8];
#pragma unroll
    for (int x = 0; x < 8; x++)
#pragma unroll
        for (int y = 0; y < 8; y++) acc[x][y] = 0.f;

    for (int k0 = 0; k0 < K; k0 += 16) {
        {
            const int r = bm + lr0;
            float4 a0, a1;
            if (r < M) {
                const float* src = A + (size_t)r * K + k0 + lk0;
                a0 = *(const float4*)src; a1 = *(const float4*)(src + 4);
            } else {
                a0 = make_float4(0, 0, 0, 0); a1 = a0;
            }
            As[(lk0 + 0) * 136 + lr0] = a0.x; As[(lk0 + 1) * 136 + lr0] = a0.y;
            As[(lk0 + 2) * 136 + lr0] = a0.z; As[(lk0 + 3) * 136 + lr0] = a0.w;
            As[(lk0 + 4) * 136 + lr0] = a1.x; As[(lk0 + 5) * 136 + lr0] = a1.y;
            As[(lk0 + 6) * 136 + lr0] = a1.z; As[(lk0 + 7) * 136 + lr0] = a1.w;
            const float* srcb = W + (size_t)(bn + lr0) * K + k0 + lk0;
            float4 b0 = *(const float4*)srcb; float4 b1 = *(const float4*)(srcb + 4);
            Bs[(lk0 + 0) * 136 + lr0] = b0.x; Bs[(lk0 + 1) * 136 + lr0] = b0.y;
            Bs[(lk0 + 2) * 136 + lr0] = b0.z; Bs[(lk0 + 3) * 136 + lr0] = b0.w;
            Bs[(lk0 + 4) * 136 + lr0] = b1.x; Bs[(lk0 + 5) * 136 + lr0] = b1.y;
            Bs[(lk0 + 6) * 136 + lr0] = b1.z; Bs[(lk0 + 7) * 136 + lr0] = b1.w;
        }
        __syncthreads();
#pragma unroll
        for (int kk = 0; kk < 16; kk++) {
            const float* ar = As + kk * 136 + tr;
            const float* br = Bs + kk * 136 + tc;
            float4 a0 = *(const float4*)ar, a1 = *(const float4*)(ar + 4);
            float4 b0 = *(const float4*)br, b1 = *(const float4*)(br + 4);
            float ra[8] = {a0.x, a0.y, a0.z, a0.w, a1.x, a1.y, a1.z, a1.w};
            float rb[8] = {b0.x, b0.y, b0.z, b0.w, b1.x, b1.y, b1.z, b1.w};
#pragma unroll
            for (int x = 0; x < 8; x++)
#pragma unroll
                for (int y = 0; y < 8; y++)
                    acc[x][y] = fmaf(ra[x], rb[y], acc[x][y]);
        }
        __syncthreads();
    }
#pragma unroll
    for (int x = 0; x < 8; x++) {
        const int r = bm + tr + x;
        if (r >= M) break;
        float* crow = C + (size_t)r * N + bn + tc;
#pragma unroll
        for (int y = 0; y < 8; y++) {
            float c = acc[x][y] + bias[bn + tc + y];
            if (flags & 2) c = 0.5f * c * (1.0f + erff(c * 0.70710678118654752f));
            if (flags & 1) c += crow[y];
            crow[y] = c;
        }
    }
}

// ---------------------------------------------------------------------------
// Flash dilated-attention branch
// ---------------------------------------------------------------------------
__global__ __launch_bounds__(128) void dil_branch_k(
    const float* __restrict__ Qm, const float* __restrict__ Km, const float* __restrict__ Vm,
    float* __restrict__ ofb, float* __restrict__ lfb, int w, int r) {
    __shared__ float Ks[32 * 64];
    __shared__ float Vs[32 * 64];
    __shared__ float Ss[32 * 128];
    const int nseg = L_ / w;
    int t = blockIdx.x;
    const int qt = t & 3; t >>= 2;
    const int h = t & 7; t >>= 3;
    const int seg = t % nseg; const int b = t / nseg;
    const int base = seg * w + (h & (r - 1));
    const int tid = threadIdx.x;
    const int j = qt * 128 + tid;
    const size_t rowq = (size_t)b * L_ + base + (size_t)r * j;
    const float* qp = Qm + rowq * D_ + h * DH_;
    float q[64];
#pragma unroll
    for (int d = 0; d < 64; d += 4) {
        float4 tv = *(const float4*)(qp + d);
        q[d] = tv.x; q[d + 1] = tv.y; q[d + 2] = tv.z; q[d + 3] = tv.w;
    }
    float o[64];
#pragma unroll
    for (int d = 0; d < 64; d++) o[d] = 0.f;
    float mv = -INFINITY, ls = 0.f;

    for (int kt = 0; kt < 16; kt++) {
        __syncthreads();
        for (int li = tid; li < 512; li += 128) {
            const int kk = li >> 4, dq = (li & 15) << 2;
            const size_t gp = ((size_t)b * L_ + base + (size_t)r * (kt * 32 + kk)) * D_
                              + h * DH_ + dq;
            *(float4*)(Ks + kk * 64 + dq) = *(const float4*)(Km + gp);
            *(float4*)(Vs + kk * 64 + dq) = *(const float4*)(Vm + gp);
        }
        __syncthreads();
        float tmax = -INFINITY;
#pragma unroll 1
        for (int kk = 0; kk < 32; kk++) {
            const float* kr = Ks + kk * 64;
            float s = 0.f;
#pragma unroll
            for (int d = 0; d < 64; d += 4) {
                float4 kv = *(const float4*)(kr + d);
                s = fmaf(q[d], kv.x, s);     s = fmaf(q[d + 1], kv.y, s);
                s = fmaf(q[d + 2], kv.z, s); s = fmaf(q[d + 3], kv.w, s);
            }
            s *= SCALE_;
            Ss[kk * 128 + tid] = s;
            tmax = fmaxf(tmax, s);
        }
        const float mn = fmaxf(mv, tmax);
        const float corr = __expf(mv - mn);
        ls *= corr;
#pragma unroll
        for (int d = 0; d < 64; d++) o[d] *= corr;
#pragma unroll 1
        for (int kk = 0; kk < 32; kk++) {
            const float p = __expf(Ss[kk * 128 + tid] - mn);
            ls += p;
            const float* vr = Vs + kk * 64;
#pragma unroll
            for (int d = 0; d < 64; d += 4) {
                float4 vv = *(const float4*)(vr + d);
                o[d]     = fmaf(p, vv.x, o[d]);
                o[d + 1] = fmaf(p, vv.y, o[d + 1]);
                o[d + 2] = fmaf(p, vv.z, o[d + 2]);
                o[d + 3] = fmaf(p, vv.w, o[d + 3]);
            }
        }
        mv = mn;
    }
    const float inv = 1.0f / ls;
    float* op = ofb + rowq * D_ + h * DH_;
#pragma unroll
    for (int d = 0; d < 64; d += 4) {
        float4 tv = make_float4(o[d] * inv, o[d + 1] * inv, o[d + 2] * inv, o[d + 3] * inv);
        *(float4*)(op + d) = tv;
    }
    lfb[rowq * H_ + h] = mv + logf(ls);
}

// ---------------------------------------------------------------------------
// Flash generic attention partial (split-KV)
// ---------------------------------------------------------------------------
__global__ __launch_bounds__(128) void attn_part_k(
    const float* __restrict__ Qm, const float* __restrict__ Km, const float* __restrict__ Vm,
    float* __restrict__ op_, float* __restrict__ lse_,
    int Tq, int Tk, int chunk) {
    __shared__ float Ks[32 * 64];
    __shared__ float Vs[32 * 64];
    __shared__ float Ss[32 * 128];
    const int split = blockIdx.x;
    const int b = blockIdx.y >> 3;
    const int h = blockIdx.y & 7;
    const int qt = blockIdx.z;
    const int tid = threadIdx.x;
    const int qi = qt * 128 + tid;
    const bool act = qi < Tq;
    const float* qp = Qm + ((size_t)b * Tq + (act ? qi : 0)) * D_ + h * DH_;
    float q[64];
#pragma unroll
    for (int d = 0; d < 64; d += 4) {
        float4 tv = *(const float4*)(qp + d);
        q[d] = tv.x; q[d + 1] = tv.y; q[d + 2] = tv.z; q[d + 3] = tv.w;
    }
    float o[64];
#pragma unroll
    for (int d = 0; d < 64; d++) o[d] = 0.f;
    float mv = -INFINITY, ls = 0.f;
    const int k0 = split * chunk;
    const int ntile = chunk / 32;

    for (int kt = 0; kt < ntile; kt++) {
        __syncthreads();
        for (int li = tid; li < 512; li += 128) {
            const int kk = li >> 4, dq = (li & 15) << 2;
            const size_t gp = ((size_t)b * Tk + k0 + kt * 32 + kk) * D_ + h * DH_ + dq;
            *(float4*)(Ks + kk * 64 + dq) = *(const float4*)(Km + gp);
            *(float4*)(Vs + kk * 64 + dq) = *(const float4*)(Vm + gp);
        }
        __syncthreads();
        float tmax = -INFINITY;
#pragma unroll 1
        for (int kk = 0; kk < 32; kk++) {
            const float* kr = Ks + kk * 64;
            float s = 0.f;
#pragma unroll
            for (int d = 0; d < 64; d += 4) {
                float4 kv = *(const float4*)(kr + d);
                s = fmaf(q[d], kv.x, s);     s = fmaf(q[d + 1], kv.y, s);
                s = fmaf(q[d + 2], kv.z, s); s = fmaf(q[d + 3], kv.w, s);
            }
            s *= SCALE_;
            Ss[kk * 128 + tid] = s;
            tmax = fmaxf(tmax, s);
        }
        const float mn = fmaxf(mv, tmax);
        const float corr = __expf(mv - mn);
        ls *= corr;
#pragma unroll
        for (int d = 0; d < 64; d++) o[d] *= corr;
#pragma unroll 1
        for (int kk = 0; kk < 32; kk++) {
            const float p = __expf(Ss[kk * 128 + tid] - mn);
            ls += p;
            const float* vr = Vs + kk * 64;
#pragma unroll
            for (int d = 0; d < 64; d += 4) {
                float4 vv = *(const float4*)(vr + d);
                o[d]     = fmaf(p, vv.x, o[d]);
                o[d + 1] = fmaf(p, vv.y, o[d + 1]);
                o[d + 2] = fmaf(p, vv.z, o[d + 2]);
                o[d + 3] = fmaf(p, vv.w, o[d + 3]);
            }
        }
        mv = mn;
    }
    if (act) {
        const size_t RH = (size_t)B_ * Tq * H_;
        const size_t idx = (size_t)split * RH + ((size_t)b * Tq + qi) * H_ + h;
        const float inv = 1.0f / ls;
        float* op = op_ + idx * 64;
#pragma unroll
        for (int d = 0; d < 64; d += 4) {
            float4 tv = make_float4(o[d] * inv, o[d + 1] * inv, o[d + 2] * inv, o[d + 3] * inv);
            *(float4*)(op + d) = tv;
        }
        lse_[idx] = mv + logf(ls);
    }
}

// ---------------------------------------------------------------------------
// LSE-weighted combine
// ---------------------------------------------------------------------------
__global__ __launch_bounds__(64) void combine_k(
    const float* __restrict__ op, const float* __restrict__ lse,
    float* __restrict__ out, int ns, size_t RH) {
    const size_t i = blockIdx.x;
    const int tid = threadIdx.x;
    float m = -INFINITY;
    for (int s = 0; s < ns; s++) {
        const float l = lse[(size_t)s * RH + i];
        if (l > -1e8f) m = fmaxf(m, l);
    }
    float tot = 0.f, acc = 0.f;
    for (int s = 0; s < ns; s++) {
        const float l = lse[(size_t)s * RH + i];
        if (l > -1e8f) {
            const float w = __expf(l - m);
            tot += w;
            acc = fmaf(w, op[((size_t)s * RH + i) * 64 + tid], acc);
        }
    }
    out[i * 64 + tid] = acc / tot;
}

// ---------------------------------------------------------------------------
// Host orchestration
// ---------------------------------------------------------------------------
struct SplitBufs {
    __nv_bfloat16 *ahi, *whi;
};

static inline void gemm_big(const SplitBufs& sb, const float* A, const float* W,
                            const float* bias, float* C,
                            int M, int N, int K, int flags, bool convA) {
    if (convA) split1_k<<<2048, 256>>>(A, sb.ahi, (size_t)M * K / 4);
    split1_k<<<512, 256>>>(W, sb.whi, (size_t)N * K / 4);
    dim3 g(N / 128, M / 128);
    gemm_mma1<<<g, 256, GM1_SMEM>>>(sb.ahi, sb.whi, bias, C, M, N, K, flags);
}

static inline void gemm_small(const float* A, const float* W, const float* bias, float* C,
                              int M, int N, int K, int flags) {
    dim3 g(N / 128, (M + 127) / 128);
    gemm_nt<<<g, 256>>>(A, W, bias, C, M, N, K, flags);
}

extern "C" void kernel_launch(void* const* d_in, const int* in_sizes, int n_in,
                              void* d_out, int out_size) {
    (void)in_sizes; (void)n_in; (void)out_size;
    cudaFuncSetAttribute(gemm_mma1, cudaFuncAttributeMaxDynamicSharedMemorySize, GM1_SMEM);

    const float* querys   = (const float*)d_in[0];
    const float* contexts = (const float*)d_in[1];
    const float* instr    = (const float*)d_in[2];
    const int*   coords   = (const int*)d_in[3];
    const float* pe       = (const float*)d_in[4];
    const float* qkv_w    = (const float*)d_in[5];
    const float* qkv_b    = (const float*)d_in[6];
    const float* ln_ln    = (const float*)d_in[7];
    const float* fc1_w    = (const float*)d_in[8];
    const float* fc1_b    = (const float*)d_in[9];
    const float* fc2_w    = (const float*)d_in[10];
    const float* fc2_b    = (const float*)d_in[11];
    const float* ln_fin   = (const float*)d_in[12];
    const float* sa_w     = (const float*)d_in[13];
    const float* sa_b     = (const float*)d_in[14];
    const float* sa_ln    = (const float*)d_in[15];
    const float* sa_g     = (const float*)d_in[16];
    const float* sa_f1w   = (const float*)d_in[17];
    const float* sa_f1b   = (const float*)d_in[18];
    const float* sa_f2w   = (const float*)d_in[19];
    const float* sa_f2b   = (const float*)d_in[20];
    const float* ca_w     = (const float*)d_in[21];
    const float* ca_b     = (const float*)d_in[22];
    const float* ca_ln    = (const float*)d_in[23];

    float* g;
    { void* p = nullptr; cudaGetSymbolAddress(&p, gbuf); g = (float*)p; }
    SplitBufs sb;
    { void* p = nullptr; cudaGetSymbolAddress(&p, g_ahi); sb.ahi = (__nv_bfloat16*)p; }
    { void* p = nullptr; cudaGetSymbolAddress(&p, g_whi); sb.whi = (__nv_bfloat16*)p; }

    float *X = g + OFF_X, *Hb = g + OFF_H, *Qb = g + OFF_Q, *Kb = g + OFF_K,
          *Vb = g + OFF_V, *OC = g + OFF_OC, *CTX = g + OFF_CTX, *O5 = g + OFF_O5,
          *FFb = g + OFF_FF, *LSE5 = g + OFF_LSE5, *COMB = g + OFF_COMB,
          *HS = g + OFF_HS, *OS = g + OFF_OS, *Tt = g + OFF_T, *FFS = g + OFF_FFS,
          *QRY = g + OFF_QRY, *PART = g + OFF_PART, *PLSE = g + OFF_PLSE;

    copy4_k<<<4096, 256>>>(CTX, contexts, S_ / 4);
    add_pos_k<<<B_ * L_, 128>>>(CTX, coords, pe);
    copy4_k<<<64, 256>>>(QRY, querys, (size_t)B_ * QN * D_ / 4);

    const int WS[5] = {512, 1024, 2048, 4096, 8192};
    const int RS[5] = {1, 2, 4, 8, 16};
    const int ML = B_ * L_;

    for (int i = 0; i < 2; i++) {
        copy4_k<<<4096, 256>>>(X, CTX, S_ / 4);
        for (int j = 0; j < 2; j++) {
            const int ij = i * 2 + j;
            const float* lg0 = ln_ln + (size_t)((ij * 2 + 0) * 2) * D_;
            layernorm_k<<<ML, 128>>>(X, Hb, lg0, lg0 + D_);
            const float* Wq = qkv_w + (size_t)(ij * 4) * DD;
            const float* bq = qkv_b + (size_t)(ij * 4) * D_;
            gemm_big(sb, Hb, Wq,          bq,          Qb, ML, D_, D_, 0, true);
            gemm_big(sb, Hb, Wq + DD,     bq + D_,     Kb, ML, D_, D_, 0, false);
            gemm_big(sb, Hb, Wq + 2 * DD, bq + 2 * D_, Vb, ML, D_, D_, 0, false);
            fill_k<<<2560, 256>>>(LSE5, 5 * BLH, NEGV);
            for (int br = 0; br < 5; br++) {
                const int w = WS[br], r = RS[br], nseg = L_ / w;
                dil_branch_k<<<B_ * nseg * H_ * 4, 128>>>(
                    Qb, Kb, Vb, O5 + (size_t)br * S_, LSE5 + (size_t)br * BLH, w, r);
            }
            combine_k<<<(unsigned)BLH, 64>>>(O5, LSE5, OC, 5, BLH);
            gemm_big(sb, OC, Wq + 3 * DD, bq + 3 * D_, X, ML, D_, D_, 1, true);
            const float* lg1 = ln_ln + (size_t)((ij * 2 + 1) * 2) * D_;
            layernorm_k<<<ML, 128>>>(X, Hb, lg1, lg1 + D_);
            gemm_big(sb, Hb, fc1_w + (size_t)ij * FF_ * D_, fc1_b + (size_t)ij * FF_,
                     FFb, ML, FF_, D_, 2, true);
            gemm_big(sb, FFb, fc2_w + (size_t)ij * D_ * FF_, fc2_b + (size_t)ij * D_,
                     X, ML, D_, FF_, 1, true);
        }
        layernorm_k<<<ML, 128>>>(X, CTX, ln_fin + (size_t)i * 2 * D_,
                                 ln_fin + (size_t)i * 2 * D_ + D_);
        concat_k<<<512, 256>>>(COMB, QRY, instr);
        const float* sl0 = sa_ln + (size_t)((i * 2 + 0) * 2) * D_;
        layernorm_k<<<B_ * 128, 128>>>(COMB, HS, sl0, sl0 + D_);
        const float* Ws = sa_w + (size_t)i * 4 * DD;
        const float* bs = sa_b + (size_t)i * 4 * D_;
        gemm_small(HS, Ws,          bs,          Qb, B_ * 128, D_, D_, 0);
        gemm_small(HS, Ws + DD,     bs + D_,     Kb, B_ * 128, D_, D_, 0);
        gemm_small(HS, Ws + 2 * DD, bs + 2 * D_, Vb, B_ * 128, D_, D_, 0);
        attn_part_k<<<dim3(1, B_ * H_, 1), 128>>>(Qb, Kb, Vb, PART, PLSE, 128, 128, 128);
        combine_k<<<B_ * 128 * H_, 64>>>(PART, PLSE, OS, 1, (size_t)B_ * 128 * H_);
        gemm_small(OS, Ws + 3 * DD, bs + 3 * D_, Tt, B_ * 128, D_, D_, 0);
        axpyg_k<<<128, 256>>>(COMB, Tt, sa_g + (size_t)(i * 2 + 0) * D_, SM);
        const float* sl1 = sa_ln + (size_t)((i * 2 + 1) * 2) * D_;
        layernorm_k<<<B_ * 128, 128>>>(COMB, HS, sl1, sl1 + D_);
        gemm_small(HS, sa_f1w + (size_t)i * FF_ * D_, sa_f1b + (size_t)i * FF_,
                   FFS, B_ * 128, FF_, D_, 2);
        gemm_small(FFS, sa_f2w + (size_t)i * D_ * FF_, sa_f2b + (size_t)i * D_,
                   Tt, B_ * 128, D_, FF_, 0);
        axpyg_k<<<128, 256>>>(COMB, Tt, sa_g + (size_t)(i * 2 + 1) * D_, SM);
        slice_k<<<32, 256>>>(QRY, COMB);
        const float* Wc = ca_w + (size_t)i * 4 * DD;
        const float* bc = ca_b + (size_t)i * 4 * D_;
        gemm_small(QRY, Wc, bc, Qb, B_ * QN, D_, D_, 0);
        gemm_big(sb, CTX, Wc + DD,     bc + D_,     Kb, ML, D_, D_, 0, true);
        gemm_big(sb, CTX, Wc + 2 * DD, bc + 2 * D_, Vb, ML, D_, D_, 0, false);
        attn_part_k<<<dim3(32, B_ * H_, 1), 128>>>(Qb, Kb, Vb, PART, PLSE, QN, L_, 256);
        combine_k<<<B_ * QN * H_, 64>>>(PART, PLSE, OS, 32, (size_t)B_ * QN * H_);
        gemm_small(OS, Wc + 3 * DD, bc + 3 * D_, QRY, B_ * QN, D_, D_, 1);
        layernorm_k<<<B_ * QN, 128>>>(QRY, QRY, ca_ln + (size_t)i * 2 * D_,
                                      ca_ln + (size_t)i * 2 * D_ + D_);
    }
    out_f32_k<<<32, 256>>>((float*)d_out, QRY, (size_t)B_ * QN * D_);
}